// round 4
// baseline (speedup 1.0000x reference)
#include <cuda_runtime.h>
#include <cstdint>

#define NN   50000
#define NE   1600000
#define HD   128
#define OUTC 224

// ---------------- scratch (device globals; no allocations) ----------------
__device__ float g_sc0[NN * HD];
__device__ float g_sc1[NN * HD];
__device__ float g_P[NN * HD];     // also reused as T in node update
__device__ float g_Q[NN * HD];
__device__ float g_agg[NN * HD];
__device__ int   g_deg[NN];
__device__ int   g_off[NN + 1];
__device__ int   g_cur[NN];
__device__ int   g_ssort[NE];
__device__ float g_lsort[NE];

// ---------------- helpers ----------------
__device__ __forceinline__ float silu_f(float x) {
    // x * sigmoid(x) = x / (1 + exp(-x)); MUFU ex2 + fast div
    return __fdividef(x, 1.f + __expf(-x));
}

__device__ __forceinline__ void ffma2(unsigned long long& d,
                                      unsigned long long a,
                                      unsigned long long b) {
    asm("fma.rn.f32x2 %0, %1, %2, %0;" : "+l"(d) : "l"(a), "l"(b));
}

// ---------------- split h into scalars + copy rest to output ----------------
__global__ void k_split(const float* __restrict__ h, float* __restrict__ out) {
    int i = blockIdx.x * blockDim.x + threadIdx.x;
    if (i >= NN * OUTC) return;
    int n = i / OUTC;
    int c = i - n * OUTC;
    float v = h[i];
    if (c < HD) g_sc0[n * HD + c] = v;
    else        out[i] = v;
}

__global__ void k_zero_deg() {
    int i = blockIdx.x * blockDim.x + threadIdx.x;
    if (i < NN) g_deg[i] = 0;
}

__global__ void k_hist(const int* __restrict__ recv) {
    int e = blockIdx.x * blockDim.x + threadIdx.x;
    if (e < NE) atomicAdd(&g_deg[recv[e]], 1);
}

// single-block exclusive scan over 50000 counts -> g_off, g_cur
__global__ void k_scan() {
    __shared__ int warp_sums[32];
    __shared__ int s_carry;
    int tid = threadIdx.x;
    int lane = tid & 31, w = tid >> 5;
    if (tid == 0) { s_carry = 0; g_off[0] = 0; }
    __syncthreads();
    for (int base = 0; base < NN; base += 1024) {
        int i = base + tid;
        int v = (i < NN) ? g_deg[i] : 0;
        int x = v;
        #pragma unroll
        for (int d = 1; d < 32; d <<= 1) {
            int y = __shfl_up_sync(0xffffffffu, x, d);
            if (lane >= d) x += y;
        }
        if (lane == 31) warp_sums[w] = x;
        __syncthreads();
        if (w == 0) {
            int s = warp_sums[lane];
            #pragma unroll
            for (int d = 1; d < 32; d <<= 1) {
                int y = __shfl_up_sync(0xffffffffu, s, d);
                if (lane >= d) s += y;
            }
            warp_sums[lane] = s;
        }
        __syncthreads();
        int incl = x + (w ? warp_sums[w - 1] : 0) + s_carry;
        if (i < NN) {
            g_off[i + 1] = incl;
            g_cur[i] = incl - v;   // exclusive prefix
        }
        __syncthreads();
        if (tid == 1023) s_carry = incl;
        __syncthreads();
    }
}

__global__ void k_scatter(const int* __restrict__ send,
                          const int* __restrict__ recv,
                          const float* __restrict__ elen) {
    int e = blockIdx.x * blockDim.x + threadIdx.x;
    if (e >= NE) return;
    int r = recv[e];
    int p = atomicAdd(&g_cur[r], 1);
    g_ssort[p] = send[e];
    g_lsort[p] = elen[e];
}

// ---------------- per-node edge aggregation (no float atomics) ----------------
// One block (128 threads) per receiver node; thread t owns feature t.
// pre = P[sender] + Q[recv] + len * w1_last ; agg = sum silu(pre)
__global__ void __launch_bounds__(128) k_agg(const float* __restrict__ wlast) {
    int node = blockIdx.x;
    int t = threadIdx.x;
    int beg = g_off[node];
    int end = g_off[node + 1];
    float q  = g_Q[node * HD + t];
    float wl = wlast[t];
    float acc = 0.f;
    #pragma unroll 4
    for (int e = beg; e < end; ++e) {
        int s   = __ldg(&g_ssort[e]);
        float l = __ldg(&g_lsort[e]);
        float x = __ldg(&g_P[s * HD + t]) + q + l * wl;
        acc += silu_f(x);
    }
    g_agg[node * HD + t] = acc;
}

// ---------------- fp32 GEMM, K = 128, N = 128, packed f32x2 inner loop ----------
// C[row, col] = op( A[row, :] @ B[:, col] + biasScale*bias[col] ) + resid[row, col]
// A: M x 128 row-major; B: 128 x 128 row-major; resid ld = 128; C ld = ldc.
template <int ACT>   // 0 = none, 1 = silu (applied before resid)
__global__ void __launch_bounds__(256) k_gemm(
    const float* __restrict__ A,
    const float* __restrict__ B,
    const float* __restrict__ bias,      // may be null
    const int*   __restrict__ degscale,  // null => scale 1
    const float* __restrict__ resid,     // may be null
    float* __restrict__ C, int ldc, int M)
{
    __shared__ float2 Asd[16][HD];   // A chunk, each value duplicated {a,a} (16 KB)
    __shared__ float  Bs[16][HD];    // B chunk (8 KB)

    int tid = threadIdx.x;
    int tx = tid & 15;       // col tile (8 cols)
    int ty = tid >> 4;       // row tile (8 rows)
    int blockM = blockIdx.x * 128;

    unsigned long long acc[8][4];
    #pragma unroll
    for (int i = 0; i < 8; i++)
        #pragma unroll
        for (int j = 0; j < 4; j++) acc[i][j] = 0ull;

    for (int kk = 0; kk < HD; kk += 16) {
        // load A tile: 128 rows x 16 cols = 512 float4
        #pragma unroll
        for (int r = 0; r < 2; r++) {
            int idx = tid + r * 256;
            int row = idx >> 2;
            int seg = idx & 3;
            int grow = blockM + row;
            if (grow >= M) grow = M - 1;
            float4 v = *(const float4*)(A + (size_t)grow * HD + kk + seg * 4);
            Asd[seg * 4 + 0][row] = make_float2(v.x, v.x);
            Asd[seg * 4 + 1][row] = make_float2(v.y, v.y);
            Asd[seg * 4 + 2][row] = make_float2(v.z, v.z);
            Asd[seg * 4 + 3][row] = make_float2(v.w, v.w);
        }
        // load B tile: 16 rows x 128 cols = 512 float4
        #pragma unroll
        for (int r = 0; r < 2; r++) {
            int idx = tid + r * 256;
            int brow = idx >> 5;
            int bc4  = idx & 31;
            float4 v = *(const float4*)(B + (size_t)(kk + brow) * HD + bc4 * 4);
            *(float4*)&Bs[brow][bc4 * 4] = v;
        }
        __syncthreads();

        #pragma unroll
        for (int k = 0; k < 16; k++) {
            unsigned long long a[8], b[4];
            const unsigned long long* Au =
                (const unsigned long long*)&Asd[k][ty * 8];
            #pragma unroll
            for (int i = 0; i < 8; i++) a[i] = Au[i];
            const unsigned long long* Bu =
                (const unsigned long long*)&Bs[k][tx * 8];
            #pragma unroll
            for (int j = 0; j < 4; j++) b[j] = Bu[j];
            #pragma unroll
            for (int i = 0; i < 8; i++)
                #pragma unroll
                for (int j = 0; j < 4; j++)
                    ffma2(acc[i][j], a[i], b[j]);
        }
        __syncthreads();
    }

    // epilogue
    #pragma unroll
    for (int i = 0; i < 8; i++) {
        int row = blockM + ty * 8 + i;
        if (row >= M) continue;
        float ds = degscale ? (float)degscale[row] : 1.f;
        #pragma unroll
        for (int j = 0; j < 4; j++) {
            union { unsigned long long u; float2 f; } cv;
            cv.u = acc[i][j];
            int col = tx * 8 + 2 * j;
            float v0 = cv.f.x, v1 = cv.f.y;
            if (bias) { v0 += ds * bias[col]; v1 += ds * bias[col + 1]; }
            if (ACT == 1) { v0 = silu_f(v0); v1 = silu_f(v1); }
            if (resid) {
                v0 += resid[(size_t)row * HD + col];
                v1 += resid[(size_t)row * HD + col + 1];
            }
            C[(size_t)row * ldc + col]     = v0;
            C[(size_t)row * ldc + col + 1] = v1;
        }
    }
}

// ---------------- launch ----------------
static float* sym_f(const void* s) { void* p = nullptr; cudaGetSymbolAddress(&p, s); return (float*)p; }
static int*   sym_i(const void* s) { void* p = nullptr; cudaGetSymbolAddress(&p, s); return (int*)p; }

extern "C" void kernel_launch(void* const* d_in, const int* in_sizes, int n_in,
                              void* d_out, int out_size) {
    const float* h     = (const float*)d_in[0];
    const int*   ei    = (const int*)  d_in[1];
    const float* elen  = (const float*)d_in[2];
    const float* mp_w1 = (const float*)d_in[3];
    const float* mp_b1 = (const float*)d_in[4];
    const float* mp_w2 = (const float*)d_in[5];
    const float* mp_b2 = (const float*)d_in[6];
    const float* nu_w1 = (const float*)d_in[7];
    const float* nu_b1 = (const float*)d_in[8];
    const float* nu_w2 = (const float*)d_in[9];
    const float* nu_b2 = (const float*)d_in[10];
    float* out = (float*)d_out;

    const int* send = ei;
    const int* recv = ei + NE;

    float* sc[2] = { sym_f(g_sc0), sym_f(g_sc1) };
    float* P   = sym_f(g_P);
    float* Q   = sym_f(g_Q);
    float* agg = sym_f(g_agg);
    int*   deg = sym_i(g_deg);

    const int GEMM_GRID = (NN + 127) / 128;   // 391

    // split h -> scalars (g_sc0) + rest -> out[:,128:224]
    k_split<<<(NN * OUTC + 255) / 256, 256>>>(h, out);

    // counting sort of edges by receiver
    k_zero_deg<<<(NN + 255) / 256, 256>>>();
    k_hist<<<(NE + 255) / 256, 256>>>(recv);
    k_scan<<<1, 1024>>>();
    k_scatter<<<(NE + 255) / 256, 256>>>(send, recv, elen);

    int cur = 0;
    for (int l = 0; l < 2; l++) {
        const float* w1 = mp_w1 + (size_t)l * 257 * HD;
        const float* b1 = mp_b1 + (size_t)l * HD;
        const float* w2 = mp_w2 + (size_t)l * HD * HD;
        const float* b2 = mp_b2 + (size_t)l * HD;

        // P = scalars @ w1[0:128];  Q = scalars @ w1[128:256] + b1
        k_gemm<0><<<GEMM_GRID, 256>>>(sc[cur], w1,            nullptr, nullptr, nullptr, P, HD, NN);
        k_gemm<0><<<GEMM_GRID, 256>>>(sc[cur], w1 + 128 * HD, b1,      nullptr, nullptr, Q, HD, NN);

        // agg[r] = sum_e silu(P[send] + Q[r] + len * w1[256])
        k_agg<<<NN, 128>>>(w1 + 256 * HD);

        // scalars' = scalars + agg @ w2 + deg * b2
        k_gemm<0><<<GEMM_GRID, 256>>>(agg, w2, b2, deg, sc[cur], sc[1 - cur], HD, NN);
        cur ^= 1;
    }

    // node update: T = silu(scalars @ nu_w1 + nu_b1)  (reuse P as T)
    k_gemm<1><<<GEMM_GRID, 256>>>(sc[cur], nu_w1, nu_b1, nullptr, nullptr, P, HD, NN);
    // out[:, :128] = scalars + T @ nu_w2 + nu_b2
    k_gemm<0><<<GEMM_GRID, 256>>>(P, nu_w2, nu_b2, nullptr, sc[cur], out, OUTC, NN);
}

// round 6
// speedup vs baseline: 1.3773x; 1.3773x over previous
#include <cuda_runtime.h>
#include <cstdint>

#define NN   50000
#define NE   1600000
#define HD   128
#define OUTC 224

// ---------------- scratch (device globals; no allocations) ----------------
__device__ float g_sc0[NN * HD];
__device__ float g_sc1[NN * HD];
__device__ float g_P[NN * HD];     // also reused as T in node update
__device__ float g_Q[NN * HD];
__device__ float g_agg[NN * HD];
__device__ int   g_deg[NN];
__device__ int   g_off[NN + 1];
__device__ int   g_cur[NN];
__device__ int   g_bsum[64];
__device__ int2  g_esort[NE];      // {sender, float_as_int(len)}

// ---------------- helpers ----------------
__device__ __forceinline__ float silu_f(float x) {
    return __fdividef(x, 1.f + __expf(-x));
}

__device__ __forceinline__ void ffma2(unsigned long long& d,
                                      unsigned long long a,
                                      unsigned long long b) {
    asm("fma.rn.f32x2 %0, %1, %2, %0;" : "+l"(d) : "l"(a), "l"(b));
}

// ---------------- copy rest channels straight to output ----------------
__global__ void k_copy_rest(const float* __restrict__ h, float* __restrict__ out) {
    int i = blockIdx.x * blockDim.x + threadIdx.x;
    if (i >= NN * (OUTC - HD)) return;
    int n = i / (OUTC - HD);
    int c = i - n * (OUTC - HD);
    int idx = n * OUTC + HD + c;
    out[idx] = h[idx];
}

__global__ void k_zero_deg() {
    int i = blockIdx.x * blockDim.x + threadIdx.x;
    if (i < NN) g_deg[i] = 0;
}

__global__ void k_hist(const int* __restrict__ recv) {
    int e = blockIdx.x * blockDim.x + threadIdx.x;
    if (e < NE) atomicAdd(&g_deg[recv[e]], 1);
}

// ---------------- 3-phase multi-block scan ----------------
// phase A: per-block inclusive scan (49 blocks x 1024), totals -> g_bsum
__global__ void __launch_bounds__(1024) k_scanA() {
    __shared__ int warp_sums[32];
    int tid = threadIdx.x;
    int lane = tid & 31, w = tid >> 5;
    int i = blockIdx.x * 1024 + tid;
    int v = (i < NN) ? g_deg[i] : 0;
    int x = v;
    #pragma unroll
    for (int d = 1; d < 32; d <<= 1) {
        int y = __shfl_up_sync(0xffffffffu, x, d);
        if (lane >= d) x += y;
    }
    if (lane == 31) warp_sums[w] = x;
    __syncthreads();
    if (w == 0) {
        int s = warp_sums[lane];
        #pragma unroll
        for (int d = 1; d < 32; d <<= 1) {
            int y = __shfl_up_sync(0xffffffffu, s, d);
            if (lane >= d) s += y;
        }
        warp_sums[lane] = s;
    }
    __syncthreads();
    int incl = x + (w ? warp_sums[w - 1] : 0);
    if (i < NN) g_off[i + 1] = incl;
    if (tid == 1023) g_bsum[blockIdx.x] = incl;
}

// phase B: exclusive scan of 49 block totals (tiny)
__global__ void k_scanB(int nblk) {
    if (threadIdx.x == 0) {
        int s = 0;
        for (int i = 0; i < nblk; i++) { int v = g_bsum[i]; g_bsum[i] = s; s += v; }
    }
}

// phase C: add block offsets, produce g_cur
__global__ void k_scanC() {
    int i = blockIdx.x * blockDim.x + threadIdx.x;
    if (i >= NN) return;
    int v = g_off[i + 1] + g_bsum[i >> 10];
    g_off[i + 1] = v;
    g_cur[i] = v - g_deg[i];
    if (i == 0) g_off[0] = 0;
}

__global__ void k_scatter(const int* __restrict__ send,
                          const int* __restrict__ recv,
                          const float* __restrict__ elen) {
    int e = blockIdx.x * blockDim.x + threadIdx.x;
    if (e >= NE) return;
    int r = recv[e];
    int p = atomicAdd(&g_cur[r], 1);
    g_esort[p] = make_int2(send[e], __float_as_int(elen[e]));
}

// ---------------- per-node edge aggregation, float2, 2 nodes/block ----------
// pre = P[sender] + Q[recv] + len * w1_last ; agg = sum silu(pre)
__global__ void __launch_bounds__(128) k_agg(const float2* __restrict__ wlast2) {
    int node = blockIdx.x * 2 + (threadIdx.x >> 6);
    int t = threadIdx.x & 63;
    if (node >= NN) return;
    int beg = g_off[node];
    int end = g_off[node + 1];
    const float2* P2 = (const float2*)g_P;
    float2 q  = ((const float2*)g_Q)[node * 64 + t];
    float2 wl = wlast2[t];
    float ax = 0.f, ay = 0.f;
    #pragma unroll 4
    for (int e = beg; e < end; ++e) {
        int2 ed = __ldg(&g_esort[e]);
        float l = __int_as_float(ed.y);
        float2 p = __ldg(&P2[ed.x * 64 + t]);
        float x0 = p.x + q.x + l * wl.x;
        float x1 = p.y + q.y + l * wl.y;
        ax += silu_f(x0);
        ay += silu_f(x1);
    }
    ((float2*)g_agg)[node * 64 + t] = make_float2(ax, ay);
}

// ---------------- fp32 GEMM, K = 128, N = 128, packed f32x2 inner loop ----------
// C[row,col] = op( A[row,:] @ B[:,col] + ds*bias[col] ) + resid[row,col]
// Thread (tx,ty): rows ty*8+i, col pairs 2*tx+32*j (conflict-free B LDS.64).
template <int ACT>   // 0 = none, 1 = silu (applied before resid)
__global__ void __launch_bounds__(256) k_gemm(
    const float* __restrict__ A, int lda,
    const float* __restrict__ B,
    const float* __restrict__ bias,      // may be null
    const int*   __restrict__ degscale,  // null => scale 1
    const float* __restrict__ resid, int ldr,
    float* __restrict__ C, int ldc, int M)
{
    __shared__ float2 Asd[16][HD];   // A chunk, each value duplicated {a,a}
    __shared__ float  Bs[16][HD];    // B chunk

    int tid = threadIdx.x;
    int tx = tid & 15;       // col group
    int ty = tid >> 4;       // row group (8 rows)
    int blockM = blockIdx.x * 128;

    unsigned long long acc[8][4];
    #pragma unroll
    for (int i = 0; i < 8; i++)
        #pragma unroll
        for (int j = 0; j < 4; j++) acc[i][j] = 0ull;

    for (int kk = 0; kk < HD; kk += 16) {
        // load A tile: 128 rows x 16 k = 512 float4
        #pragma unroll
        for (int r = 0; r < 2; r++) {
            int idx = tid + r * 256;
            int row = idx >> 2;
            int seg = idx & 3;
            int grow = blockM + row;
            if (grow >= M) grow = M - 1;
            float4 v = *(const float4*)(A + (size_t)grow * lda + kk + seg * 4);
            Asd[seg * 4 + 0][row] = make_float2(v.x, v.x);
            Asd[seg * 4 + 1][row] = make_float2(v.y, v.y);
            Asd[seg * 4 + 2][row] = make_float2(v.z, v.z);
            Asd[seg * 4 + 3][row] = make_float2(v.w, v.w);
        }
        // load B tile: 16 rows x 128 cols = 512 float4
        #pragma unroll
        for (int r = 0; r < 2; r++) {
            int idx = tid + r * 256;
            int brow = idx >> 5;
            int bc4  = idx & 31;
            float4 v = *(const float4*)(B + (size_t)(kk + brow) * HD + bc4 * 4);
            *(float4*)&Bs[brow][bc4 * 4] = v;
        }
        __syncthreads();

        #pragma unroll
        for (int k = 0; k < 16; k++) {
            unsigned long long a[8], b[4];
            const unsigned long long* Au =
                (const unsigned long long*)&Asd[k][ty * 8];
            #pragma unroll
            for (int i = 0; i < 8; i++) a[i] = Au[i];
            #pragma unroll
            for (int j = 0; j < 4; j++)
                b[j] = *(const unsigned long long*)&Bs[k][2 * tx + 32 * j];
            #pragma unroll
            for (int i = 0; i < 8; i++)
                #pragma unroll
                for (int j = 0; j < 4; j++)
                    ffma2(acc[i][j], a[i], b[j]);
        }
        __syncthreads();
    }

    // epilogue
    #pragma unroll
    for (int i = 0; i < 8; i++) {
        int row = blockM + ty * 8 + i;
        if (row >= M) continue;
        float ds = degscale ? (float)degscale[row] : 1.f;
        #pragma unroll
        for (int j = 0; j < 4; j++) {
            int col = 2 * tx + 32 * j;
            union { unsigned long long u; float2 f; } cv;
            cv.u = acc[i][j];
            float v0 = cv.f.x, v1 = cv.f.y;
            if (bias) {
                float2 bv = *(const float2*)(bias + col);
                v0 += ds * bv.x; v1 += ds * bv.y;
            }
            if (ACT == 1) { v0 = silu_f(v0); v1 = silu_f(v1); }
            if (resid) {
                float2 rv = *(const float2*)(resid + (size_t)row * ldr + col);
                v0 += rv.x; v1 += rv.y;
            }
            *(float2*)(C + (size_t)row * ldc + col) = make_float2(v0, v1);
        }
    }
}

// ---------------- launch ----------------
static float* sym_f(const void* s) { void* p = nullptr; cudaGetSymbolAddress(&p, s); return (float*)p; }
static int*   sym_i(const void* s) { void* p = nullptr; cudaGetSymbolAddress(&p, s); return (int*)p; }

extern "C" void kernel_launch(void* const* d_in, const int* in_sizes, int n_in,
                              void* d_out, int out_size) {
    const float* h     = (const float*)d_in[0];
    const int*   ei    = (const int*)  d_in[1];
    const float* elen  = (const float*)d_in[2];
    const float* mp_w1 = (const float*)d_in[3];
    const float* mp_b1 = (const float*)d_in[4];
    const float* mp_w2 = (const float*)d_in[5];
    const float* mp_b2 = (const float*)d_in[6];
    const float* nu_w1 = (const float*)d_in[7];
    const float* nu_b1 = (const float*)d_in[8];
    const float* nu_w2 = (const float*)d_in[9];
    const float* nu_b2 = (const float*)d_in[10];
    float* out = (float*)d_out;

    const int* send = ei;
    const int* recv = ei + NE;

    float* sc[2] = { sym_f(g_sc0), sym_f(g_sc1) };
    float* P   = sym_f(g_P);
    float* Q   = sym_f(g_Q);
    float* agg = sym_f(g_agg);
    int*   deg = sym_i(g_deg);

    const int GEMM_GRID = (NN + 127) / 128;   // 391
    const int SCAN_BLK  = (NN + 1023) / 1024; // 49

    // rest channels straight to output
    k_copy_rest<<<(NN * (OUTC - HD) + 255) / 256, 256>>>(h, out);

    // counting sort of edges by receiver
    k_zero_deg<<<(NN + 255) / 256, 256>>>();
    k_hist<<<(NE + 255) / 256, 256>>>(recv);
    k_scanA<<<SCAN_BLK, 1024>>>();
    k_scanB<<<1, 32>>>(SCAN_BLK);
    k_scanC<<<(NN + 255) / 256, 256>>>();
    k_scatter<<<(NE + 255) / 256, 256>>>(send, recv, elen);

    // layer-0 scalars live in h (lda = 224); afterwards in sc buffers (lda = 128)
    const float* cur = h;  int curld = OUTC;
    int flip = 0;
    for (int l = 0; l < 2; l++) {
        const float* w1 = mp_w1 + (size_t)l * 257 * HD;
        const float* b1 = mp_b1 + (size_t)l * HD;
        const float* w2 = mp_w2 + (size_t)l * HD * HD;
        const float* b2 = mp_b2 + (size_t)l * HD;

        // P = scalars @ w1[0:128];  Q = scalars @ w1[128:256] + b1
        k_gemm<0><<<GEMM_GRID, 256>>>(cur, curld, w1,            nullptr, nullptr,
                                      nullptr, 0, P, HD, NN);
        k_gemm<0><<<GEMM_GRID, 256>>>(cur, curld, w1 + 128 * HD, b1,      nullptr,
                                      nullptr, 0, Q, HD, NN);

        // agg[r] = sum_e silu(P[send] + Q[r] + len * w1[256])
        k_agg<<<(NN + 1) / 2, 128>>>((const float2*)(w1 + 256 * HD));

        // scalars' = scalars + agg @ w2 + deg * b2
        k_gemm<0><<<GEMM_GRID, 256>>>(agg, HD, w2, b2, deg,
                                      cur, curld, sc[flip], HD, NN);
        cur = sc[flip]; curld = HD; flip ^= 1;
    }

    // node update: T = silu(scalars @ nu_w1 + nu_b1)  (reuse P as T)
    k_gemm<1><<<GEMM_GRID, 256>>>(cur, HD, nu_w1, nu_b1, nullptr,
                                  nullptr, 0, P, HD, NN);
    // out[:, :128] = scalars + T @ nu_w2 + nu_b2
    k_gemm<0><<<GEMM_GRID, 256>>>(P, HD, nu_w2, nu_b2, nullptr,
                                  cur, HD, out, OUTC, NN);
}

// round 7
// speedup vs baseline: 1.7309x; 1.2568x over previous
#include <cuda_runtime.h>
#include <cstdint>

#define NN   50000
#define NE   1600000
#define HD   128
#define OUTC 224

// ---------------- scratch (device globals; no allocations) ----------------
__device__ float g_sc0[NN * HD];
__device__ float g_sc1[NN * HD];
__device__ float g_P[NN * HD];     // also reused as T in node update
__device__ float g_Q[NN * HD];
__device__ float g_agg[NN * HD];
__device__ int   g_deg[NN];
__device__ int   g_off[NN + 1];
__device__ int   g_cur[NN];
__device__ int   g_bsum[64];
__device__ int2  g_esort[NE];      // {sender, float_as_int(len)}

// ---------------- helpers ----------------
__device__ __forceinline__ float silu_f(float x) {
    // x*sigmoid(x) = h + h*tanh(h), h = x/2 ; single MUFU (tanh.approx)
    float h = 0.5f * x, t;
    asm("tanh.approx.f32 %0, %1;" : "=f"(t) : "f"(h));
    return fmaf(h, t, h);
}

__device__ __forceinline__ void ffma2(unsigned long long& d,
                                      unsigned long long a,
                                      unsigned long long b) {
    asm("fma.rn.f32x2 %0, %1, %2, %0;" : "+l"(d) : "l"(a), "l"(b));
}

// ---------------- copy rest channels straight to output ----------------
__global__ void k_copy_rest(const float* __restrict__ h, float* __restrict__ out) {
    int i = blockIdx.x * blockDim.x + threadIdx.x;
    if (i >= NN * (OUTC - HD)) return;
    int n = i / (OUTC - HD);
    int c = i - n * (OUTC - HD);
    int idx = n * OUTC + HD + c;
    out[idx] = h[idx];
}

__global__ void k_zero_deg() {
    int i = blockIdx.x * blockDim.x + threadIdx.x;
    if (i < NN) g_deg[i] = 0;
}

__global__ void k_hist(const int* __restrict__ recv) {
    int e = blockIdx.x * blockDim.x + threadIdx.x;
    if (e < NE) atomicAdd(&g_deg[recv[e]], 1);
}

// ---------------- 3-phase multi-block scan ----------------
__global__ void __launch_bounds__(1024) k_scanA() {
    __shared__ int warp_sums[32];
    int tid = threadIdx.x;
    int lane = tid & 31, w = tid >> 5;
    int i = blockIdx.x * 1024 + tid;
    int v = (i < NN) ? g_deg[i] : 0;
    int x = v;
    #pragma unroll
    for (int d = 1; d < 32; d <<= 1) {
        int y = __shfl_up_sync(0xffffffffu, x, d);
        if (lane >= d) x += y;
    }
    if (lane == 31) warp_sums[w] = x;
    __syncthreads();
    if (w == 0) {
        int s = warp_sums[lane];
        #pragma unroll
        for (int d = 1; d < 32; d <<= 1) {
            int y = __shfl_up_sync(0xffffffffu, s, d);
            if (lane >= d) s += y;
        }
        warp_sums[lane] = s;
    }
    __syncthreads();
    int incl = x + (w ? warp_sums[w - 1] : 0);
    if (i < NN) g_off[i + 1] = incl;
    if (tid == 1023) g_bsum[blockIdx.x] = incl;
}

__global__ void k_scanB(int nblk) {
    if (threadIdx.x == 0) {
        int s = 0;
        for (int i = 0; i < nblk; i++) { int v = g_bsum[i]; g_bsum[i] = s; s += v; }
    }
}

__global__ void k_scanC() {
    int i = blockIdx.x * blockDim.x + threadIdx.x;
    if (i >= NN) return;
    int v = g_off[i + 1] + g_bsum[i >> 10];
    g_off[i + 1] = v;
    g_cur[i] = v - g_deg[i];
    if (i == 0) g_off[0] = 0;
}

__global__ void k_scatter(const int* __restrict__ send,
                          const int* __restrict__ recv,
                          const float* __restrict__ elen) {
    int e = blockIdx.x * blockDim.x + threadIdx.x;
    if (e >= NE) return;
    int r = recv[e];
    int p = atomicAdd(&g_cur[r], 1);
    g_esort[p] = make_int2(send[e], __float_as_int(elen[e]));
}

// ---------------- per-node edge aggregation, float4, 32 threads/node ----------
// pre = P[sender] + Q[recv] + len * w1_last ; agg = sum silu(pre)
__global__ void __launch_bounds__(256) k_agg(const float4* __restrict__ wlast4) {
    int node = blockIdx.x * 8 + (threadIdx.x >> 5);
    int t = threadIdx.x & 31;
    if (node >= NN) return;
    int beg = g_off[node];
    int end = g_off[node + 1];
    const float4* P4 = (const float4*)g_P;
    float4 q  = ((const float4*)g_Q)[node * 32 + t];
    float4 wl = wlast4[t];
    float4 a = make_float4(0.f, 0.f, 0.f, 0.f);
    #pragma unroll 2
    for (int e = beg; e < end; ++e) {
        int2 ed = __ldg(&g_esort[e]);
        float l = __int_as_float(ed.y);
        float4 p = __ldg(&P4[ed.x * 32 + t]);
        a.x += silu_f(p.x + fmaf(l, wl.x, q.x));
        a.y += silu_f(p.y + fmaf(l, wl.y, q.y));
        a.z += silu_f(p.z + fmaf(l, wl.z, q.z));
        a.w += silu_f(p.w + fmaf(l, wl.w, q.w));
    }
    ((float4*)g_agg)[node * 32 + t] = a;
}

// ---------------- fp32 GEMM, K=128, N=128, f32x2 inner loop, reg-prefetch ----
// C[row,col] = op( A[row,:] @ B[:,col] + ds*bias[col] ) + resid[row,col]
template <int ACT>   // 0 = none, 1 = silu (applied before resid)
__global__ void __launch_bounds__(256, 2) k_gemm(
    const float* __restrict__ A, int lda,
    const float* __restrict__ B,
    const float* __restrict__ bias,      // may be null
    const int*   __restrict__ degscale,  // null => scale 1
    const float* __restrict__ resid, int ldr,
    float* __restrict__ C, int ldc, int M)
{
    __shared__ float2 Asd[16][HD];   // A chunk, each value duplicated {a,a}
    __shared__ float  Bs[16][HD];    // B chunk

    int tid = threadIdx.x;
    int tx = tid & 15;       // col group: cols 2*tx + 32*j
    int ty = tid >> 4;       // row group: rows ty*8 + i
    int blockM = blockIdx.x * 128;

    // A-load indices (per thread, 2 loads)
    int aRow0 = tid >> 2,          aSeg0 = tid & 3;
    int aRow1 = (tid + 256) >> 2,  aSeg1 = (tid + 256) & 3;
    int gRow0 = blockM + aRow0; if (gRow0 >= M) gRow0 = M - 1;
    int gRow1 = blockM + aRow1; if (gRow1 >= M) gRow1 = M - 1;
    // B-load indices
    int bRow0 = tid >> 5,          bC0 = (tid & 31) * 4;
    int bRow1 = (tid + 256) >> 5,  bC1 = ((tid + 256) & 31) * 4;

    unsigned long long acc[8][4];
    #pragma unroll
    for (int i = 0; i < 8; i++)
        #pragma unroll
        for (int j = 0; j < 4; j++) acc[i][j] = 0ull;

    // prefetch chunk 0
    float4 pa0 = *(const float4*)(A + (size_t)gRow0 * lda + aSeg0 * 4);
    float4 pa1 = *(const float4*)(A + (size_t)gRow1 * lda + aSeg1 * 4);
    float4 pb0 = *(const float4*)(B + (size_t)bRow0 * HD + bC0);
    float4 pb1 = *(const float4*)(B + (size_t)bRow1 * HD + bC1);

    #pragma unroll
    for (int kk = 0; kk < HD; kk += 16) {
        // stage current chunk into smem
        Asd[aSeg0 * 4 + 0][aRow0] = make_float2(pa0.x, pa0.x);
        Asd[aSeg0 * 4 + 1][aRow0] = make_float2(pa0.y, pa0.y);
        Asd[aSeg0 * 4 + 2][aRow0] = make_float2(pa0.z, pa0.z);
        Asd[aSeg0 * 4 + 3][aRow0] = make_float2(pa0.w, pa0.w);
        Asd[aSeg1 * 4 + 0][aRow1] = make_float2(pa1.x, pa1.x);
        Asd[aSeg1 * 4 + 1][aRow1] = make_float2(pa1.y, pa1.y);
        Asd[aSeg1 * 4 + 2][aRow1] = make_float2(pa1.z, pa1.z);
        Asd[aSeg1 * 4 + 3][aRow1] = make_float2(pa1.w, pa1.w);
        *(float4*)&Bs[bRow0][bC0] = pb0;
        *(float4*)&Bs[bRow1][bC1] = pb1;
        __syncthreads();

        // prefetch next chunk (overlaps with compute below)
        if (kk + 16 < HD) {
            pa0 = *(const float4*)(A + (size_t)gRow0 * lda + kk + 16 + aSeg0 * 4);
            pa1 = *(const float4*)(A + (size_t)gRow1 * lda + kk + 16 + aSeg1 * 4);
            pb0 = *(const float4*)(B + (size_t)(kk + 16 + bRow0) * HD + bC0);
            pb1 = *(const float4*)(B + (size_t)(kk + 16 + bRow1) * HD + bC1);
        }

        #pragma unroll
        for (int k = 0; k < 16; k++) {
            unsigned long long a[8], b[4];
            const unsigned long long* Au =
                (const unsigned long long*)&Asd[k][ty * 8];
            #pragma unroll
            for (int i = 0; i < 8; i++) a[i] = Au[i];
            #pragma unroll
            for (int j = 0; j < 4; j++)
                b[j] = *(const unsigned long long*)&Bs[k][2 * tx + 32 * j];
            #pragma unroll
            for (int i = 0; i < 8; i++)
                #pragma unroll
                for (int j = 0; j < 4; j++)
                    ffma2(acc[i][j], a[i], b[j]);
        }
        __syncthreads();
    }

    // epilogue
    #pragma unroll
    for (int i = 0; i < 8; i++) {
        int row = blockM + ty * 8 + i;
        if (row >= M) continue;
        float ds = degscale ? (float)degscale[row] : 1.f;
        #pragma unroll
        for (int j = 0; j < 4; j++) {
            int col = 2 * tx + 32 * j;
            union { unsigned long long u; float2 f; } cv;
            cv.u = acc[i][j];
            float v0 = cv.f.x, v1 = cv.f.y;
            if (bias) {
                float2 bv = *(const float2*)(bias + col);
                v0 += ds * bv.x; v1 += ds * bv.y;
            }
            if (ACT == 1) { v0 = silu_f(v0); v1 = silu_f(v1); }
            if (resid) {
                float2 rv = *(const float2*)(resid + (size_t)row * ldr + col);
                v0 += rv.x; v1 += rv.y;
            }
            *(float2*)(C + (size_t)row * ldc + col) = make_float2(v0, v1);
        }
    }
}

// ---------------- launch ----------------
static float* sym_f(const void* s) { void* p = nullptr; cudaGetSymbolAddress(&p, s); return (float*)p; }
static int*   sym_i(const void* s) { void* p = nullptr; cudaGetSymbolAddress(&p, s); return (int*)p; }

extern "C" void kernel_launch(void* const* d_in, const int* in_sizes, int n_in,
                              void* d_out, int out_size) {
    const float* h     = (const float*)d_in[0];
    const int*   ei    = (const int*)  d_in[1];
    const float* elen  = (const float*)d_in[2];
    const float* mp_w1 = (const float*)d_in[3];
    const float* mp_b1 = (const float*)d_in[4];
    const float* mp_w2 = (const float*)d_in[5];
    const float* mp_b2 = (const float*)d_in[6];
    const float* nu_w1 = (const float*)d_in[7];
    const float* nu_b1 = (const float*)d_in[8];
    const float* nu_w2 = (const float*)d_in[9];
    const float* nu_b2 = (const float*)d_in[10];
    float* out = (float*)d_out;

    const int* send = ei;
    const int* recv = ei + NE;

    float* sc[2] = { sym_f(g_sc0), sym_f(g_sc1) };
    float* P   = sym_f(g_P);
    float* Q   = sym_f(g_Q);
    float* agg = sym_f(g_agg);
    int*   deg = sym_i(g_deg);

    const int GEMM_GRID = (NN + 127) / 128;   // 391
    const int SCAN_BLK  = (NN + 1023) / 1024; // 49

    // rest channels straight to output
    k_copy_rest<<<(NN * (OUTC - HD) + 255) / 256, 256>>>(h, out);

    // counting sort of edges by receiver
    k_zero_deg<<<(NN + 255) / 256, 256>>>();
    k_hist<<<(NE + 255) / 256, 256>>>(recv);
    k_scanA<<<SCAN_BLK, 1024>>>();
    k_scanB<<<1, 32>>>(SCAN_BLK);
    k_scanC<<<(NN + 255) / 256, 256>>>();
    k_scatter<<<(NE + 255) / 256, 256>>>(send, recv, elen);

    // layer-0 scalars live in h (lda = 224); afterwards in sc buffers (lda = 128)
    const float* cur = h;  int curld = OUTC;
    int flip = 0;
    for (int l = 0; l < 2; l++) {
        const float* w1 = mp_w1 + (size_t)l * 257 * HD;
        const float* b1 = mp_b1 + (size_t)l * HD;
        const float* w2 = mp_w2 + (size_t)l * HD * HD;
        const float* b2 = mp_b2 + (size_t)l * HD;

        // P = scalars @ w1[0:128];  Q = scalars @ w1[128:256] + b1
        k_gemm<0><<<GEMM_GRID, 256>>>(cur, curld, w1,            nullptr, nullptr,
                                      nullptr, 0, P, HD, NN);
        k_gemm<0><<<GEMM_GRID, 256>>>(cur, curld, w1 + 128 * HD, b1,      nullptr,
                                      nullptr, 0, Q, HD, NN);

        // agg[r] = sum_e silu(P[send] + Q[r] + len * w1[256])
        k_agg<<<(NN + 7) / 8, 256>>>((const float4*)(w1 + 256 * HD));

        // scalars' = scalars + agg @ w2 + deg * b2
        k_gemm<0><<<GEMM_GRID, 256>>>(agg, HD, w2, b2, deg,
                                      cur, curld, sc[flip], HD, NN);
        cur = sc[flip]; curld = HD; flip ^= 1;
    }

    // node update: T = silu(scalars @ nu_w1 + nu_b1)  (reuse P as T)
    k_gemm<1><<<GEMM_GRID, 256>>>(cur, HD, nu_w1, nu_b1, nullptr,
                                  nullptr, 0, P, HD, NN);
    // out[:, :128] = scalars + T @ nu_w2 + nu_b2
    k_gemm<0><<<GEMM_GRID, 256>>>(P, HD, nu_w2, nu_b2, nullptr,
                                  cur, HD, out, OUTC, NN);
}

// round 9
// speedup vs baseline: 2.2087x; 1.2761x over previous
#include <cuda_runtime.h>
#include <cuda_bf16.h>
#include <cstdint>

#define NN   50000
#define NE   1600000
#define HD   128
#define OUTC 224

// ---------------- scratch (device globals; no allocations) ----------------
__device__ float g_sc0[NN * HD];
__device__ float g_sc1[NN * HD];
__device__ float g_P[NN * HD];     // also reused as T in node update
__device__ float g_Q[NN * HD];
__device__ float g_agg[NN * HD];
__device__ int   g_deg[NN];
__device__ int   g_off[NN + 1];
__device__ int   g_cur[NN];
__device__ int   g_bsum[64];
__device__ int2  g_esort[NE];      // {sender, float_as_int(len)}
// pre-converted weights: 8 matrices, Bt[n][k] dense bf16 hi/lo (w[k][n] transposed)
__device__ __nv_bfloat16 g_wimg_hi[8 * 16384];
__device__ __nv_bfloat16 g_wimg_lo[8 * 16384];

// ---------------- helpers ----------------
__device__ __forceinline__ float silu_f(float x) {
    float h = 0.5f * x, t;
    asm("tanh.approx.f32 %0, %1;" : "=f"(t) : "f"(h));
    return fmaf(h, t, h);
}

__device__ __forceinline__ void mma_bf16(float* c, const uint32_t* a, const uint32_t* b) {
    asm volatile(
        "mma.sync.aligned.m16n8k16.row.col.f32.bf16.bf16.f32 "
        "{%0,%1,%2,%3}, {%4,%5,%6,%7}, {%8,%9}, {%0,%1,%2,%3};"
        : "+f"(c[0]), "+f"(c[1]), "+f"(c[2]), "+f"(c[3])
        : "r"(a[0]), "r"(a[1]), "r"(a[2]), "r"(a[3]), "r"(b[0]), "r"(b[1]));
}

// ---------------- small kernels (from the 574us passing version) ----------------
__global__ void k_copy_rest(const float* __restrict__ h, float* __restrict__ out) {
    int i = blockIdx.x * blockDim.x + threadIdx.x;
    if (i >= NN * (OUTC - HD)) return;
    int n = i / (OUTC - HD);
    int c = i - n * (OUTC - HD);
    int idx = n * OUTC + HD + c;
    out[idx] = h[idx];
}

__global__ void k_zero_deg() {
    int i = blockIdx.x * blockDim.x + threadIdx.x;
    if (i < NN) g_deg[i] = 0;
}

__global__ void k_hist(const int* __restrict__ recv) {
    int e = blockIdx.x * blockDim.x + threadIdx.x;
    if (e < NE) atomicAdd(&g_deg[recv[e]], 1);
}

__global__ void __launch_bounds__(1024) k_scanA() {
    __shared__ int warp_sums[32];
    int tid = threadIdx.x;
    int lane = tid & 31, w = tid >> 5;
    int i = blockIdx.x * 1024 + tid;
    int v = (i < NN) ? g_deg[i] : 0;
    int x = v;
    #pragma unroll
    for (int d = 1; d < 32; d <<= 1) {
        int y = __shfl_up_sync(0xffffffffu, x, d);
        if (lane >= d) x += y;
    }
    if (lane == 31) warp_sums[w] = x;
    __syncthreads();
    if (w == 0) {
        int s = warp_sums[lane];
        #pragma unroll
        for (int d = 1; d < 32; d <<= 1) {
            int y = __shfl_up_sync(0xffffffffu, s, d);
            if (lane >= d) s += y;
        }
        warp_sums[lane] = s;
    }
    __syncthreads();
    int incl = x + (w ? warp_sums[w - 1] : 0);
    if (i < NN) g_off[i + 1] = incl;
    if (tid == 1023) g_bsum[blockIdx.x] = incl;
}

__global__ void k_scanB(int nblk) {
    if (threadIdx.x == 0) {
        int s = 0;
        for (int i = 0; i < nblk; i++) { int v = g_bsum[i]; g_bsum[i] = s; s += v; }
    }
}

__global__ void k_scanC() {
    int i = blockIdx.x * blockDim.x + threadIdx.x;
    if (i >= NN) return;
    int v = g_off[i + 1] + g_bsum[i >> 10];
    g_off[i + 1] = v;
    g_cur[i] = v - g_deg[i];
    if (i == 0) g_off[0] = 0;
}

__global__ void k_scatter(const int* __restrict__ send,
                          const int* __restrict__ recv,
                          const float* __restrict__ elen) {
    int e = blockIdx.x * blockDim.x + threadIdx.x;
    if (e >= NE) return;
    int r = recv[e];
    int p = atomicAdd(&g_cur[r], 1);
    g_esort[p] = make_int2(send[e], __float_as_int(elen[e]));
}

__global__ void __launch_bounds__(256) k_agg(const float4* __restrict__ wlast4) {
    int node = blockIdx.x * 8 + (threadIdx.x >> 5);
    int t = threadIdx.x & 31;
    if (node >= NN) return;
    int beg = g_off[node];
    int end = g_off[node + 1];
    const float4* P4 = (const float4*)g_P;
    float4 q  = ((const float4*)g_Q)[node * 32 + t];
    float4 wl = wlast4[t];
    float4 a = make_float4(0.f, 0.f, 0.f, 0.f);
    #pragma unroll 2
    for (int e = beg; e < end; ++e) {
        int2 ed = __ldg(&g_esort[e]);
        float l = __int_as_float(ed.y);
        float4 p = __ldg(&P4[ed.x * 32 + t]);
        a.x += silu_f(p.x + fmaf(l, wl.x, q.x));
        a.y += silu_f(p.y + fmaf(l, wl.y, q.y));
        a.z += silu_f(p.z + fmaf(l, wl.z, q.z));
        a.w += silu_f(p.w + fmaf(l, wl.w, q.w));
    }
    ((float4*)g_agg)[node * 32 + t] = a;
}

// ---------------- weight pre-convert: w[k][n] fp32 -> Bt[n][k] bf16 hi/lo ----
struct WSrc { const float* p[8]; };

__global__ void k_wconv(WSrc ws) {
    int mat = blockIdx.y;
    int t = blockIdx.x * blockDim.x + threadIdx.x;   // 0..2047
    if (t >= 2048) return;
    int n  = t & 127;
    int k0 = (t >> 7) * 8;
    const float* src = ws.p[mat];
    __nv_bfloat16 hi[8], lo[8];
    #pragma unroll
    for (int i = 0; i < 8; i++) {
        float x = src[(k0 + i) * HD + n];      // w[k][n] -> Bt[n][k]
        __nv_bfloat16 h = __float2bfloat16(x);
        hi[i] = h;
        lo[i] = __float2bfloat16(x - __bfloat162float(h));
    }
    size_t off = (size_t)mat * 16384 + n * 128 + k0;
    *(uint4*)&g_wimg_hi[off] = *(uint4*)hi;
    *(uint4*)&g_wimg_lo[off] = *(uint4*)lo;
}

// ---------------- split-bf16 HMMA GEMM, tile 128x128, K=128 -------------------
// C[row,col] = op( A[row,:] @ W[:,col] + ds*bias[col] ) + resid[row,col]
// 512 thr = 16 warps, warp tile 32x32 (2 m-frags x 4 n-frags of m16n8k16).
// smem: A_hi/A_lo/B_hi/B_lo, each [128][136] bf16 (pitch 136 -> conflict-free).
#define PITCH 136
#define TILE_B (128 * PITCH * 2)        // 34816
#define SM_AHI 0
#define SM_ALO (TILE_B)
#define SM_BHI (2 * TILE_B)
#define SM_BLO (3 * TILE_B)
#define SM_TOTAL (4 * TILE_B)           // 139264

template <int ACT>   // 0 = none, 1 = silu (applied before resid)
__global__ void __launch_bounds__(512, 1) k_gemm_mma(
    const float* __restrict__ A, int lda,
    int mat,
    const float* __restrict__ bias,
    const int*   __restrict__ degscale,
    const float* __restrict__ resid, int ldr,
    float* __restrict__ C, int ldc, int M)
{
    extern __shared__ char smem[];
    __nv_bfloat16* sAh = (__nv_bfloat16*)(smem + SM_AHI);
    __nv_bfloat16* sAl = (__nv_bfloat16*)(smem + SM_ALO);
    __nv_bfloat16* sBh = (__nv_bfloat16*)(smem + SM_BHI);
    __nv_bfloat16* sBl = (__nv_bfloat16*)(smem + SM_BLO);

    int tid = threadIdx.x;
    int wid = tid >> 5, lid = tid & 31;
    int blockM = blockIdx.x * 128;

    // ---- load + convert A tile: thread -> row tid>>2, 32-col quarter ----
    {
        int r  = tid >> 2;
        int c0 = (tid & 3) * 32;
        int grow = blockM + r; if (grow >= M) grow = M - 1;
        const float* arow = A + (size_t)grow * lda + c0;
        #pragma unroll
        for (int g = 0; g < 4; g++) {
            float4 f0 = *(const float4*)(arow + g * 8);
            float4 f1 = *(const float4*)(arow + g * 8 + 4);
            float xs[8] = {f0.x, f0.y, f0.z, f0.w, f1.x, f1.y, f1.z, f1.w};
            __nv_bfloat16 hi[8], lo[8];
            #pragma unroll
            for (int i = 0; i < 8; i++) {
                __nv_bfloat16 h = __float2bfloat16(xs[i]);
                hi[i] = h;
                lo[i] = __float2bfloat16(xs[i] - __bfloat162float(h));
            }
            int off = r * PITCH + c0 + g * 8;
            *(uint4*)&sAh[off] = *(uint4*)hi;
            *(uint4*)&sAl[off] = *(uint4*)lo;
        }
    }
    // ---- copy B images (dense [n][k] -> pitch 136) ----
    {
        int r = tid >> 2;
        int s = (tid & 3) * 32;     // 32 bf16 = 64 B = 4 uint4
        const uint4* shi = (const uint4*)&g_wimg_hi[(size_t)mat * 16384 + r * 128 + s];
        const uint4* slo = (const uint4*)&g_wimg_lo[(size_t)mat * 16384 + r * 128 + s];
        uint4* dhi = (uint4*)&sBh[r * PITCH + s];
        uint4* dlo = (uint4*)&sBl[r * PITCH + s];
        #pragma unroll
        for (int i = 0; i < 4; i++) { dhi[i] = shi[i]; dlo[i] = slo[i]; }
    }
    __syncthreads();

    // ---- MMA mainloop ----
    int warp_m = wid >> 2, warp_n = wid & 3;
    int row0 = warp_m * 32;
    int col0 = warp_n * 32;
    int g2 = lid >> 2, tq = lid & 3;

    float acc[2][4][4];
    #pragma unroll
    for (int mi = 0; mi < 2; mi++)
        #pragma unroll
        for (int nj = 0; nj < 4; nj++)
            #pragma unroll
            for (int q = 0; q < 4; q++) acc[mi][nj][q] = 0.f;

    // pair-index views (each uint32 = 2 bf16, pairs contiguous in k)
    const uint32_t* Ah = (const uint32_t*)sAh;
    const uint32_t* Al = (const uint32_t*)sAl;
    const uint32_t* Bh = (const uint32_t*)sBh;
    const uint32_t* Bl = (const uint32_t*)sBl;
    const int HP = PITCH / 2;   // 68 pairs per row

    #pragma unroll 2
    for (int ks = 0; ks < 8; ks++) {
        int kp = ks * 8;   // pair offset of k-step (16 k = 8 pairs)
        uint32_t ah[2][4], al[2][4], bh[4][2], bl[4][2];
        #pragma unroll
        for (int mi = 0; mi < 2; mi++) {
            int r1 = (row0 + mi * 16 + g2) * HP;
            int r2 = r1 + 8 * HP;
            ah[mi][0] = Ah[r1 + kp + tq];
            ah[mi][1] = Ah[r2 + kp + tq];
            ah[mi][2] = Ah[r1 + kp + 4 + tq];
            ah[mi][3] = Ah[r2 + kp + 4 + tq];
            al[mi][0] = Al[r1 + kp + tq];
            al[mi][1] = Al[r2 + kp + tq];
            al[mi][2] = Al[r1 + kp + 4 + tq];
            al[mi][3] = Al[r2 + kp + 4 + tq];
        }
        #pragma unroll
        for (int nj = 0; nj < 4; nj++) {
            int rn = (col0 + nj * 8 + g2) * HP;
            bh[nj][0] = Bh[rn + kp + tq];
            bh[nj][1] = Bh[rn + kp + 4 + tq];
            bl[nj][0] = Bl[rn + kp + tq];
            bl[nj][1] = Bl[rn + kp + 4 + tq];
        }
        #pragma unroll
        for (int mi = 0; mi < 2; mi++)
            #pragma unroll
            for (int nj = 0; nj < 4; nj++) {
                mma_bf16(acc[mi][nj], ah[mi], bh[nj]);
                mma_bf16(acc[mi][nj], ah[mi], bl[nj]);
                mma_bf16(acc[mi][nj], al[mi], bh[nj]);
            }
    }

    // ---- epilogue: fragments -> global, fused bias/deg/silu/resid ----
    #pragma unroll
    for (int mi = 0; mi < 2; mi++) {
        int r1 = blockM + row0 + mi * 16 + g2;
        int r2 = r1 + 8;
        float ds1 = 1.f, ds2 = 1.f;
        if (degscale) {
            if (r1 < M) ds1 = (float)degscale[r1];
            if (r2 < M) ds2 = (float)degscale[r2];
        }
        #pragma unroll
        for (int nj = 0; nj < 4; nj++) {
            int col = col0 + nj * 8 + tq * 2;
            float2 bv = make_float2(0.f, 0.f);
            if (bias) bv = *(const float2*)(bias + col);
            if (r1 < M) {
                float v0 = acc[mi][nj][0], v1 = acc[mi][nj][1];
                if (bias) { v0 += ds1 * bv.x; v1 += ds1 * bv.y; }
                if (ACT == 1) { v0 = silu_f(v0); v1 = silu_f(v1); }
                if (resid) {
                    float2 rv = *(const float2*)(resid + (size_t)r1 * ldr + col);
                    v0 += rv.x; v1 += rv.y;
                }
                *(float2*)(C + (size_t)r1 * ldc + col) = make_float2(v0, v1);
            }
            if (r2 < M) {
                float v0 = acc[mi][nj][2], v1 = acc[mi][nj][3];
                if (bias) { v0 += ds2 * bv.x; v1 += ds2 * bv.y; }
                if (ACT == 1) { v0 = silu_f(v0); v1 = silu_f(v1); }
                if (resid) {
                    float2 rv = *(const float2*)(resid + (size_t)r2 * ldr + col);
                    v0 += rv.x; v1 += rv.y;
                }
                *(float2*)(C + (size_t)r2 * ldc + col) = make_float2(v0, v1);
            }
        }
    }
}

// ---------------- launch ----------------
static float* sym_f(const void* s) { void* p = nullptr; cudaGetSymbolAddress(&p, s); return (float*)p; }
static int*   sym_i(const void* s) { void* p = nullptr; cudaGetSymbolAddress(&p, s); return (int*)p; }

extern "C" void kernel_launch(void* const* d_in, const int* in_sizes, int n_in,
                              void* d_out, int out_size) {
    const float* h     = (const float*)d_in[0];
    const int*   ei    = (const int*)  d_in[1];
    const float* elen  = (const float*)d_in[2];
    const float* mp_w1 = (const float*)d_in[3];
    const float* mp_b1 = (const float*)d_in[4];
    const float* mp_w2 = (const float*)d_in[5];
    const float* mp_b2 = (const float*)d_in[6];
    const float* nu_w1 = (const float*)d_in[7];
    const float* nu_b1 = (const float*)d_in[8];
    const float* nu_w2 = (const float*)d_in[9];
    const float* nu_b2 = (const float*)d_in[10];
    float* out = (float*)d_out;

    const int* send = ei;
    const int* recv = ei + NE;

    float* sc[2] = { sym_f(g_sc0), sym_f(g_sc1) };
    float* P   = sym_f(g_P);
    float* Q   = sym_f(g_Q);
    float* agg = sym_f(g_agg);
    int*   deg = sym_i(g_deg);

    static int attr_done = 0;
    if (!attr_done) {
        cudaFuncSetAttribute(k_gemm_mma<0>, cudaFuncAttributeMaxDynamicSharedMemorySize, SM_TOTAL);
        cudaFuncSetAttribute(k_gemm_mma<1>, cudaFuncAttributeMaxDynamicSharedMemorySize, SM_TOTAL);
        attr_done = 1;
    }

    const int GEMM_GRID = (NN + 127) / 128;   // 391
    const int SCAN_BLK  = (NN + 1023) / 1024; // 49

    // weight images: 0..2 layer0 {w1a,w1b,w2}, 3..5 layer1, 6 nu_w1, 7 nu_w2
    WSrc ws;
    ws.p[0] = mp_w1;                 ws.p[1] = mp_w1 + 128 * HD;
    ws.p[2] = mp_w2;
    ws.p[3] = mp_w1 + 257 * HD;      ws.p[4] = mp_w1 + 257 * HD + 128 * HD;
    ws.p[5] = mp_w2 + HD * HD;
    ws.p[6] = nu_w1;                 ws.p[7] = nu_w2;
    k_wconv<<<dim3(8, 8), 256>>>(ws);

    // rest channels straight to output
    k_copy_rest<<<(NN * (OUTC - HD) + 255) / 256, 256>>>(h, out);

    // counting sort of edges by receiver
    k_zero_deg<<<(NN + 255) / 256, 256>>>();
    k_hist<<<(NE + 255) / 256, 256>>>(recv);
    k_scanA<<<SCAN_BLK, 1024>>>();
    k_scanB<<<1, 32>>>(SCAN_BLK);
    k_scanC<<<(NN + 255) / 256, 256>>>();
    k_scatter<<<(NE + 255) / 256, 256>>>(send, recv, elen);

    // layer-0 scalars live in h (lda = 224); afterwards in sc buffers (lda = 128)
    const float* cur = h;  int curld = OUTC;
    int flip = 0;
    for (int l = 0; l < 2; l++) {
        const float* w1 = mp_w1 + (size_t)l * 257 * HD;
        const float* b1 = mp_b1 + (size_t)l * HD;
        const float* b2 = mp_b2 + (size_t)l * HD;

        // P = scalars @ w1[0:128];  Q = scalars @ w1[128:256] + b1
        k_gemm_mma<0><<<GEMM_GRID, 512, SM_TOTAL>>>(cur, curld, 3 * l + 0, nullptr, nullptr,
                                                    nullptr, 0, P, HD, NN);
        k_gemm_mma<0><<<GEMM_GRID, 512, SM_TOTAL>>>(cur, curld, 3 * l + 1, b1,      nullptr,
                                                    nullptr, 0, Q, HD, NN);

        // agg[r] = sum_e silu(P[send] + Q[r] + len * w1[256])
        k_agg<<<(NN + 7) / 8, 256>>>((const float4*)(w1 + 256 * HD));

        // scalars' = scalars + agg @ w2 + deg * b2
        k_gemm_mma<0><<<GEMM_GRID, 512, SM_TOTAL>>>(agg, HD, 3 * l + 2, b2, deg,
                                                    cur, curld, sc[flip], HD, NN);
        cur = sc[flip]; curld = HD; flip ^= 1;
    }

    // node update: T = silu(scalars @ nu_w1 + nu_b1)  (reuse P as T)
    k_gemm_mma<1><<<GEMM_GRID, 512, SM_TOTAL>>>(cur, HD, 6, nu_b1, nullptr,
                                                nullptr, 0, P, HD, NN);
    // out[:, :128] = scalars + T @ nu_w2 + nu_b2
    k_gemm_mma<0><<<GEMM_GRID, 512, SM_TOTAL>>>(P, HD, 7, nu_b2, nullptr,
                                                cur, HD, out, OUTC, NN);
}

// round 10
// speedup vs baseline: 2.2528x; 1.0199x over previous
#include <cuda_runtime.h>
#include <cuda_bf16.h>
#include <cuda_fp16.h>
#include <cstdint>

#define NN   50000
#define NE   1600000
#define HD   128
#define OUTC 224

// ---------------- scratch (device globals; no allocations) ----------------
__device__ float g_sc0[NN * HD];
__device__ float g_sc1[NN * HD];
__device__ float g_P[NN * HD];     // holds P as __half (half the bytes used)
__device__ float g_Q[NN * HD];
__device__ float g_agg[NN * HD];
__device__ int   g_deg[NN];
__device__ int   g_off[NN + 1];
__device__ int   g_cur[NN];
__device__ int   g_bsum[64];
__device__ int2  g_esort[NE];      // {sender, float_as_int(len)}
// pre-converted weights: 8 matrices, Bt[n][k] dense bf16 hi/lo (w[k][n] transposed)
__device__ __nv_bfloat16 g_wimg_hi[8 * 16384];
__device__ __nv_bfloat16 g_wimg_lo[8 * 16384];

// ---------------- helpers ----------------
__device__ __forceinline__ float silu_f(float x) {
    float h = 0.5f * x, t;
    asm("tanh.approx.f32 %0, %1;" : "=f"(t) : "f"(h));
    return fmaf(h, t, h);
}

__device__ __forceinline__ void mma_bf16(float* c, const uint32_t* a, const uint32_t* b) {
    asm volatile(
        "mma.sync.aligned.m16n8k16.row.col.f32.bf16.bf16.f32 "
        "{%0,%1,%2,%3}, {%4,%5,%6,%7}, {%8,%9}, {%0,%1,%2,%3};"
        : "+f"(c[0]), "+f"(c[1]), "+f"(c[2]), "+f"(c[3])
        : "r"(a[0]), "r"(a[1]), "r"(a[2]), "r"(a[3]), "r"(b[0]), "r"(b[1]));
}

// ---------------- small kernels ----------------
__global__ void k_copy_rest(const float* __restrict__ h, float* __restrict__ out) {
    int i = blockIdx.x * blockDim.x + threadIdx.x;
    if (i >= NN * (OUTC - HD)) return;
    int n = i / (OUTC - HD);
    int c = i - n * (OUTC - HD);
    int idx = n * OUTC + HD + c;
    out[idx] = h[idx];
}

__global__ void k_zero_deg() {
    int i = blockIdx.x * blockDim.x + threadIdx.x;
    if (i < NN) g_deg[i] = 0;
}

__global__ void k_hist(const int* __restrict__ recv) {
    int e = blockIdx.x * blockDim.x + threadIdx.x;
    if (e < NE) atomicAdd(&g_deg[recv[e]], 1);
}

__global__ void __launch_bounds__(1024) k_scanA() {
    __shared__ int warp_sums[32];
    int tid = threadIdx.x;
    int lane = tid & 31, w = tid >> 5;
    int i = blockIdx.x * 1024 + tid;
    int v = (i < NN) ? g_deg[i] : 0;
    int x = v;
    #pragma unroll
    for (int d = 1; d < 32; d <<= 1) {
        int y = __shfl_up_sync(0xffffffffu, x, d);
        if (lane >= d) x += y;
    }
    if (lane == 31) warp_sums[w] = x;
    __syncthreads();
    if (w == 0) {
        int s = warp_sums[lane];
        #pragma unroll
        for (int d = 1; d < 32; d <<= 1) {
            int y = __shfl_up_sync(0xffffffffu, s, d);
            if (lane >= d) s += y;
        }
        warp_sums[lane] = s;
    }
    __syncthreads();
    int incl = x + (w ? warp_sums[w - 1] : 0);
    if (i < NN) g_off[i + 1] = incl;
    if (tid == 1023) g_bsum[blockIdx.x] = incl;
}

__global__ void k_scanB(int nblk) {
    if (threadIdx.x == 0) {
        int s = 0;
        for (int i = 0; i < nblk; i++) { int v = g_bsum[i]; g_bsum[i] = s; s += v; }
    }
}

__global__ void k_scanC() {
    int i = blockIdx.x * blockDim.x + threadIdx.x;
    if (i >= NN) return;
    int v = g_off[i + 1] + g_bsum[i >> 10];
    g_off[i + 1] = v;
    g_cur[i] = v - g_deg[i];
    if (i == 0) g_off[0] = 0;
}

__global__ void k_scatter(const int* __restrict__ send,
                          const int* __restrict__ recv,
                          const float* __restrict__ elen) {
    int e = blockIdx.x * blockDim.x + threadIdx.x;
    if (e >= NE) return;
    int r = recv[e];
    int p = atomicAdd(&g_cur[r], 1);
    g_esort[p] = make_int2(send[e], __float_as_int(elen[e]));
}

// ---------------- per-node edge aggregation (P now fp16) ----------------
__global__ void __launch_bounds__(256) k_agg(const float4* __restrict__ wlast4) {
    int node = blockIdx.x * 8 + (threadIdx.x >> 5);
    int t = threadIdx.x & 31;
    if (node >= NN) return;
    int beg = g_off[node];
    int end = g_off[node + 1];
    const uint2* P4h = (const uint2*)g_P;   // 4 halves per uint2
    float4 q  = ((const float4*)g_Q)[node * 32 + t];
    float4 wl = wlast4[t];
    float4 a = make_float4(0.f, 0.f, 0.f, 0.f);
    #pragma unroll 2
    for (int e = beg; e < end; ++e) {
        int2 ed = __ldg(&g_esort[e]);
        float l = __int_as_float(ed.y);
        uint2 pu = __ldg(&P4h[ed.x * 32 + t]);
        float2 p01 = __half22float2(*(const __half2*)&pu.x);
        float2 p23 = __half22float2(*(const __half2*)&pu.y);
        a.x += silu_f(p01.x + fmaf(l, wl.x, q.x));
        a.y += silu_f(p01.y + fmaf(l, wl.y, q.y));
        a.z += silu_f(p23.x + fmaf(l, wl.z, q.z));
        a.w += silu_f(p23.y + fmaf(l, wl.w, q.w));
    }
    ((float4*)g_agg)[node * 32 + t] = a;
}

// ---------------- weight pre-convert: w[k][n] fp32 -> Bt[n][k] bf16 hi/lo ----
struct WSrc { const float* p[8]; };

__global__ void k_wconv(WSrc ws) {
    int mat = blockIdx.y;
    int t = blockIdx.x * blockDim.x + threadIdx.x;   // 0..2047
    if (t >= 2048) return;
    int n  = t & 127;
    int k0 = (t >> 7) * 8;
    const float* src = ws.p[mat];
    __nv_bfloat16 hi[8], lo[8];
    #pragma unroll
    for (int i = 0; i < 8; i++) {
        float x = src[(k0 + i) * HD + n];
        __nv_bfloat16 h = __float2bfloat16(x);
        hi[i] = h;
        lo[i] = __float2bfloat16(x - __bfloat162float(h));
    }
    size_t off = (size_t)mat * 16384 + n * 128 + k0;
    *(uint4*)&g_wimg_hi[off] = *(uint4*)hi;
    *(uint4*)&g_wimg_lo[off] = *(uint4*)lo;
}

// ---------------- shared GEMM machinery ----------------
#define PITCH 136
#define HP    (PITCH / 2)
#define IMG   (128 * PITCH * 2)         // 34816 bytes per bf16 image

// A tile load + split-convert into two smem images (pitch layout)
__device__ __forceinline__ void load_convert_A(
    const float* __restrict__ A, int lda, int blockM, int M,
    __nv_bfloat16* sAh, __nv_bfloat16* sAl, int tid)
{
    int r  = tid >> 2;
    int c0 = (tid & 3) * 32;
    int grow = blockM + r; if (grow >= M) grow = M - 1;
    const float* arow = A + (size_t)grow * lda + c0;
    #pragma unroll
    for (int g = 0; g < 4; g++) {
        float4 f0 = *(const float4*)(arow + g * 8);
        float4 f1 = *(const float4*)(arow + g * 8 + 4);
        float xs[8] = {f0.x, f0.y, f0.z, f0.w, f1.x, f1.y, f1.z, f1.w};
        __nv_bfloat16 hi[8], lo[8];
        #pragma unroll
        for (int i = 0; i < 8; i++) {
            __nv_bfloat16 h = __float2bfloat16(xs[i]);
            hi[i] = h;
            lo[i] = __float2bfloat16(xs[i] - __bfloat162float(h));
        }
        int off = r * PITCH + c0 + g * 8;
        *(uint4*)&sAh[off] = *(uint4*)hi;
        *(uint4*)&sAl[off] = *(uint4*)lo;
    }
}

// copy one pre-converted weight image pair into smem (pitch layout)
__device__ __forceinline__ void copy_B(
    int mat, __nv_bfloat16* sBh, __nv_bfloat16* sBl, int tid)
{
    int r = tid >> 2;
    int s = (tid & 3) * 32;
    const uint4* shi = (const uint4*)&g_wimg_hi[(size_t)mat * 16384 + r * 128 + s];
    const uint4* slo = (const uint4*)&g_wimg_lo[(size_t)mat * 16384 + r * 128 + s];
    uint4* dhi = (uint4*)&sBh[r * PITCH + s];
    uint4* dlo = (uint4*)&sBl[r * PITCH + s];
    #pragma unroll
    for (int i = 0; i < 4; i++) { dhi[i] = shi[i]; dlo[i] = slo[i]; }
}

// load this warp's A fragments for k-step ks
__device__ __forceinline__ void load_afrag(
    const uint32_t* Ah, const uint32_t* Al, int row0, int g2, int tq, int ks,
    uint32_t ah[2][4], uint32_t al[2][4])
{
    int kp = ks * 8;
    #pragma unroll
    for (int mi = 0; mi < 2; mi++) {
        int r1 = (row0 + mi * 16 + g2) * HP;
        int r2 = r1 + 8 * HP;
        ah[mi][0] = Ah[r1 + kp + tq];
        ah[mi][1] = Ah[r2 + kp + tq];
        ah[mi][2] = Ah[r1 + kp + 4 + tq];
        ah[mi][3] = Ah[r2 + kp + 4 + tq];
        al[mi][0] = Al[r1 + kp + tq];
        al[mi][1] = Al[r2 + kp + tq];
        al[mi][2] = Al[r1 + kp + 4 + tq];
        al[mi][3] = Al[r2 + kp + 4 + tq];
    }
}

// 3-term MMA of one k-step against one B image pair
__device__ __forceinline__ void mma_step(
    const uint32_t* Bh, const uint32_t* Bl, int col0, int g2, int tq, int ks,
    uint32_t ah[2][4], uint32_t al[2][4], float acc[2][4][4])
{
    int kp = ks * 8;
    #pragma unroll
    for (int nj = 0; nj < 4; nj++) {
        int rn = (col0 + nj * 8 + g2) * HP;
        uint32_t bh[2], bl[2];
        bh[0] = Bh[rn + kp + tq];
        bh[1] = Bh[rn + kp + 4 + tq];
        bl[0] = Bl[rn + kp + tq];
        bl[1] = Bl[rn + kp + 4 + tq];
        #pragma unroll
        for (int mi = 0; mi < 2; mi++) {
            mma_bf16(acc[mi][nj], ah[mi], bh);
            mma_bf16(acc[mi][nj], ah[mi], bl);
            mma_bf16(acc[mi][nj], al[mi], bh);
        }
    }
}

// ---------------- fused P+Q GEMM: A once, two weight matrices -----------------
// P (fp16, no bias) and Q (fp32, bias b1)
#define PQ_SMEM (6 * IMG)
__global__ void __launch_bounds__(512, 1) k_gemm_pq(
    const float* __restrict__ A, int lda, int mat0,
    const float* __restrict__ b1,
    __half* __restrict__ Pout, float* __restrict__ Qout, int M)
{
    extern __shared__ char smem[];
    __nv_bfloat16* sAh = (__nv_bfloat16*)(smem);
    __nv_bfloat16* sAl = (__nv_bfloat16*)(smem + IMG);
    __nv_bfloat16* sB[4] = {
        (__nv_bfloat16*)(smem + 2 * IMG), (__nv_bfloat16*)(smem + 3 * IMG),
        (__nv_bfloat16*)(smem + 4 * IMG), (__nv_bfloat16*)(smem + 5 * IMG) };

    int tid = threadIdx.x;
    int wid = tid >> 5, lid = tid & 31;
    int blockM = blockIdx.x * 128;

    load_convert_A(A, lda, blockM, M, sAh, sAl, tid);
    copy_B(mat0,     sB[0], sB[1], tid);
    copy_B(mat0 + 1, sB[2], sB[3], tid);
    __syncthreads();

    int row0 = (wid >> 2) * 32;
    int col0 = (wid & 3) * 32;
    int g2 = lid >> 2, tq = lid & 3;

    float acc[2][2][4][4];
    #pragma unroll
    for (int m = 0; m < 2; m++)
        for (int mi = 0; mi < 2; mi++)
            for (int nj = 0; nj < 4; nj++)
                for (int q = 0; q < 4; q++) acc[m][mi][nj][q] = 0.f;

    const uint32_t* Ah = (const uint32_t*)sAh;
    const uint32_t* Al = (const uint32_t*)sAl;

    for (int ks = 0; ks < 8; ks++) {
        uint32_t ah[2][4], al[2][4];
        load_afrag(Ah, Al, row0, g2, tq, ks, ah, al);
        mma_step((const uint32_t*)sB[0], (const uint32_t*)sB[1],
                 col0, g2, tq, ks, ah, al, acc[0]);
        mma_step((const uint32_t*)sB[2], (const uint32_t*)sB[3],
                 col0, g2, tq, ks, ah, al, acc[1]);
    }

    // epilogue
    #pragma unroll
    for (int mi = 0; mi < 2; mi++) {
        int r1 = blockM + row0 + mi * 16 + g2;
        int r2 = r1 + 8;
        #pragma unroll
        for (int nj = 0; nj < 4; nj++) {
            int col = col0 + nj * 8 + tq * 2;
            float2 bv = *(const float2*)(b1 + col);
            if (r1 < M) {
                *(__half2*)(Pout + (size_t)r1 * HD + col) =
                    __float22half2_rn(make_float2(acc[0][mi][nj][0], acc[0][mi][nj][1]));
                *(float2*)(Qout + (size_t)r1 * HD + col) =
                    make_float2(acc[1][mi][nj][0] + bv.x, acc[1][mi][nj][1] + bv.y);
            }
            if (r2 < M) {
                *(__half2*)(Pout + (size_t)r2 * HD + col) =
                    __float22half2_rn(make_float2(acc[0][mi][nj][2], acc[0][mi][nj][3]));
                *(float2*)(Qout + (size_t)r2 * HD + col) =
                    make_float2(acc[1][mi][nj][2] + bv.x, acc[1][mi][nj][3] + bv.y);
            }
        }
    }
}

// ---------------- W2 GEMM: C = agg @ w2 + deg*b2 + resid ----------------------
#define W2_SMEM (4 * IMG)
__global__ void __launch_bounds__(512, 1) k_gemm_w2(
    const float* __restrict__ A, int mat,
    const float* __restrict__ bias, const int* __restrict__ degscale,
    const float* __restrict__ resid, int ldr,
    float* __restrict__ C, int M)
{
    extern __shared__ char smem[];
    __nv_bfloat16* sAh = (__nv_bfloat16*)(smem);
    __nv_bfloat16* sAl = (__nv_bfloat16*)(smem + IMG);
    __nv_bfloat16* sBh = (__nv_bfloat16*)(smem + 2 * IMG);
    __nv_bfloat16* sBl = (__nv_bfloat16*)(smem + 3 * IMG);

    int tid = threadIdx.x;
    int wid = tid >> 5, lid = tid & 31;
    int blockM = blockIdx.x * 128;

    load_convert_A(A, HD, blockM, M, sAh, sAl, tid);
    copy_B(mat, sBh, sBl, tid);
    __syncthreads();

    int row0 = (wid >> 2) * 32;
    int col0 = (wid & 3) * 32;
    int g2 = lid >> 2, tq = lid & 3;

    float acc[2][4][4];
    #pragma unroll
    for (int mi = 0; mi < 2; mi++)
        for (int nj = 0; nj < 4; nj++)
            for (int q = 0; q < 4; q++) acc[mi][nj][q] = 0.f;

    const uint32_t* Ah = (const uint32_t*)sAh;
    const uint32_t* Al = (const uint32_t*)sAl;

    #pragma unroll 2
    for (int ks = 0; ks < 8; ks++) {
        uint32_t ah[2][4], al[2][4];
        load_afrag(Ah, Al, row0, g2, tq, ks, ah, al);
        mma_step((const uint32_t*)sBh, (const uint32_t*)sBl,
                 col0, g2, tq, ks, ah, al, acc);
    }

    #pragma unroll
    for (int mi = 0; mi < 2; mi++) {
        int r1 = blockM + row0 + mi * 16 + g2;
        int r2 = r1 + 8;
        float ds1 = (r1 < M) ? (float)degscale[r1] : 0.f;
        float ds2 = (r2 < M) ? (float)degscale[r2] : 0.f;
        #pragma unroll
        for (int nj = 0; nj < 4; nj++) {
            int col = col0 + nj * 8 + tq * 2;
            float2 bv = *(const float2*)(bias + col);
            if (r1 < M) {
                float2 rv = *(const float2*)(resid + (size_t)r1 * ldr + col);
                *(float2*)(C + (size_t)r1 * HD + col) = make_float2(
                    acc[mi][nj][0] + ds1 * bv.x + rv.x,
                    acc[mi][nj][1] + ds1 * bv.y + rv.y);
            }
            if (r2 < M) {
                float2 rv = *(const float2*)(resid + (size_t)r2 * ldr + col);
                *(float2*)(C + (size_t)r2 * HD + col) = make_float2(
                    acc[mi][nj][2] + ds2 * bv.x + rv.x,
                    acc[mi][nj][3] + ds2 * bv.y + rv.y);
            }
        }
    }
}

// ---------------- fused node-update: out = sc + silu(sc@W1+b1)@W2 + b2 --------
// T stays in smem (bf16 hi/lo split), second MMA chained in-kernel.
#define NU_SMEM (6 * IMG)
__global__ void __launch_bounds__(512, 1) k_gemm_nu(
    const float* __restrict__ A, int lda,
    const float* __restrict__ b1, const float* __restrict__ b2,
    float* __restrict__ out, int ldc, int M)
{
    extern __shared__ char smem[];
    __nv_bfloat16* sAh  = (__nv_bfloat16*)(smem);            // later: T hi
    __nv_bfloat16* sAl  = (__nv_bfloat16*)(smem + IMG);      // later: T lo
    __nv_bfloat16* sB1h = (__nv_bfloat16*)(smem + 2 * IMG);
    __nv_bfloat16* sB1l = (__nv_bfloat16*)(smem + 3 * IMG);
    __nv_bfloat16* sB2h = (__nv_bfloat16*)(smem + 4 * IMG);
    __nv_bfloat16* sB2l = (__nv_bfloat16*)(smem + 5 * IMG);

    int tid = threadIdx.x;
    int wid = tid >> 5, lid = tid & 31;
    int blockM = blockIdx.x * 128;

    load_convert_A(A, lda, blockM, M, sAh, sAl, tid);
    copy_B(6, sB1h, sB1l, tid);
    copy_B(7, sB2h, sB2l, tid);
    __syncthreads();

    int row0 = (wid >> 2) * 32;
    int col0 = (wid & 3) * 32;
    int g2 = lid >> 2, tq = lid & 3;

    float acc[2][4][4];
    #pragma unroll
    for (int mi = 0; mi < 2; mi++)
        for (int nj = 0; nj < 4; nj++)
            for (int q = 0; q < 4; q++) acc[mi][nj][q] = 0.f;

    const uint32_t* Ah = (const uint32_t*)sAh;
    const uint32_t* Al = (const uint32_t*)sAl;

    // ---- MMA 1: A @ nu_w1 ----
    #pragma unroll 2
    for (int ks = 0; ks < 8; ks++) {
        uint32_t ah[2][4], al[2][4];
        load_afrag(Ah, Al, row0, g2, tq, ks, ah, al);
        mma_step((const uint32_t*)sB1h, (const uint32_t*)sB1l,
                 col0, g2, tq, ks, ah, al, acc);
    }
    __syncthreads();   // everyone done reading A images

    // ---- T = silu(acc + b1), split to bf16 hi/lo, store into A slots ----
    {
        uint32_t* Th = (uint32_t*)sAh;
        uint32_t* Tl = (uint32_t*)sAl;
        #pragma unroll
        for (int mi = 0; mi < 2; mi++) {
            int rt1 = row0 + mi * 16 + g2;
            int rt2 = rt1 + 8;
            #pragma unroll
            for (int nj = 0; nj < 4; nj++) {
                int col = col0 + nj * 8 + tq * 2;
                float2 bv = *(const float2*)(b1 + col);
                float v0 = silu_f(acc[mi][nj][0] + bv.x);
                float v1 = silu_f(acc[mi][nj][1] + bv.y);
                float v2 = silu_f(acc[mi][nj][2] + bv.x);
                float v3 = silu_f(acc[mi][nj][3] + bv.y);
                __nv_bfloat16 h0 = __float2bfloat16(v0), h1 = __float2bfloat16(v1);
                __nv_bfloat16 h2 = __float2bfloat16(v2), h3 = __float2bfloat16(v3);
                __nv_bfloat162 hi1 = {h0, h1}, hi2 = {h2, h3};
                __nv_bfloat162 lo1 = {__float2bfloat16(v0 - __bfloat162float(h0)),
                                      __float2bfloat16(v1 - __bfloat162float(h1))};
                __nv_bfloat162 lo2 = {__float2bfloat16(v2 - __bfloat162float(h2)),
                                      __float2bfloat16(v3 - __bfloat162float(h3))};
                Th[rt1 * HP + col / 2] = *(uint32_t*)&hi1;
                Tl[rt1 * HP + col / 2] = *(uint32_t*)&lo1;
                Th[rt2 * HP + col / 2] = *(uint32_t*)&hi2;
                Tl[rt2 * HP + col / 2] = *(uint32_t*)&lo2;
                acc[mi][nj][0] = 0.f; acc[mi][nj][1] = 0.f;
                acc[mi][nj][2] = 0.f; acc[mi][nj][3] = 0.f;
            }
        }
    }
    __syncthreads();

    // ---- MMA 2: T @ nu_w2 ----
    #pragma unroll 2
    for (int ks = 0; ks < 8; ks++) {
        uint32_t ah[2][4], al[2][4];
        load_afrag(Ah, Al, row0, g2, tq, ks, ah, al);
        mma_step((const uint32_t*)sB2h, (const uint32_t*)sB2l,
                 col0, g2, tq, ks, ah, al, acc);
    }

    // ---- epilogue: + b2 + resid(scalars), write out (ldc = OUTC) ----
    #pragma unroll
    for (int mi = 0; mi < 2; mi++) {
        int r1 = blockM + row0 + mi * 16 + g2;
        int r2 = r1 + 8;
        #pragma unroll
        for (int nj = 0; nj < 4; nj++) {
            int col = col0 + nj * 8 + tq * 2;
            float2 bv = *(const float2*)(b2 + col);
            if (r1 < M) {
                float2 rv = *(const float2*)(A + (size_t)r1 * lda + col);
                *(float2*)(out + (size_t)r1 * ldc + col) = make_float2(
                    acc[mi][nj][0] + bv.x + rv.x, acc[mi][nj][1] + bv.y + rv.y);
            }
            if (r2 < M) {
                float2 rv = *(const float2*)(A + (size_t)r2 * lda + col);
                *(float2*)(out + (size_t)r2 * ldc + col) = make_float2(
                    acc[mi][nj][2] + bv.x + rv.x, acc[mi][nj][3] + bv.y + rv.y);
            }
        }
    }
}

// ---------------- launch ----------------
static float* sym_f(const void* s) { void* p = nullptr; cudaGetSymbolAddress(&p, s); return (float*)p; }
static int*   sym_i(const void* s) { void* p = nullptr; cudaGetSymbolAddress(&p, s); return (int*)p; }

extern "C" void kernel_launch(void* const* d_in, const int* in_sizes, int n_in,
                              void* d_out, int out_size) {
    const float* h     = (const float*)d_in[0];
    const int*   ei    = (const int*)  d_in[1];
    const float* elen  = (const float*)d_in[2];
    const float* mp_w1 = (const float*)d_in[3];
    const float* mp_b1 = (const float*)d_in[4];
    const float* mp_w2 = (const float*)d_in[5];
    const float* mp_b2 = (const float*)d_in[6];
    const float* nu_w1 = (const float*)d_in[7];
    const float* nu_b1 = (const float*)d_in[8];
    const float* nu_w2 = (const float*)d_in[9];
    const float* nu_b2 = (const float*)d_in[10];
    float* out = (float*)d_out;

    const int* send = ei;
    const int* recv = ei + NE;

    float* sc[2] = { sym_f(g_sc0), sym_f(g_sc1) };
    __half* Ph = (__half*)sym_f(g_P);
    float* Q   = sym_f(g_Q);
    float* agg = sym_f(g_agg);
    int*   deg = sym_i(g_deg);

    static int attr_done = 0;
    if (!attr_done) {
        cudaFuncSetAttribute(k_gemm_pq, cudaFuncAttributeMaxDynamicSharedMemorySize, PQ_SMEM);
        cudaFuncSetAttribute(k_gemm_w2, cudaFuncAttributeMaxDynamicSharedMemorySize, W2_SMEM);
        cudaFuncSetAttribute(k_gemm_nu, cudaFuncAttributeMaxDynamicSharedMemorySize, NU_SMEM);
        attr_done = 1;
    }

    const int GEMM_GRID = (NN + 127) / 128;   // 391
    const int SCAN_BLK  = (NN + 1023) / 1024; // 49

    // weight images: 0..2 layer0 {w1a,w1b,w2}, 3..5 layer1, 6 nu_w1, 7 nu_w2
    WSrc ws;
    ws.p[0] = mp_w1;                 ws.p[1] = mp_w1 + 128 * HD;
    ws.p[2] = mp_w2;
    ws.p[3] = mp_w1 + 257 * HD;      ws.p[4] = mp_w1 + 257 * HD + 128 * HD;
    ws.p[5] = mp_w2 + HD * HD;
    ws.p[6] = nu_w1;                 ws.p[7] = nu_w2;
    k_wconv<<<dim3(8, 8), 256>>>(ws);

    // rest channels straight to output
    k_copy_rest<<<(NN * (OUTC - HD) + 255) / 256, 256>>>(h, out);

    // counting sort of edges by receiver
    k_zero_deg<<<(NN + 255) / 256, 256>>>();
    k_hist<<<(NE + 255) / 256, 256>>>(recv);
    k_scanA<<<SCAN_BLK, 1024>>>();
    k_scanB<<<1, 32>>>(SCAN_BLK);
    k_scanC<<<(NN + 255) / 256, 256>>>();
    k_scatter<<<(NE + 255) / 256, 256>>>(send, recv, elen);

    // layer-0 scalars live in h (lda = 224); afterwards in sc buffers (lda = 128)
    const float* cur = h;  int curld = OUTC;
    int flip = 0;
    for (int l = 0; l < 2; l++) {
        const float* w1 = mp_w1 + (size_t)l * 257 * HD;
        const float* b1 = mp_b1 + (size_t)l * HD;
        const float* b2 = mp_b2 + (size_t)l * HD;

        // P (fp16) and Q (fp32) in one pass over A
        k_gemm_pq<<<GEMM_GRID, 512, PQ_SMEM>>>(cur, curld, 3 * l, b1, Ph, Q, NN);

        // agg[r] = sum_e silu(P[send] + Q[r] + len * w1[256])
        k_agg<<<(NN + 7) / 8, 256>>>((const float4*)(w1 + 256 * HD));

        // scalars' = scalars + agg @ w2 + deg * b2
        k_gemm_w2<<<GEMM_GRID, 512, W2_SMEM>>>(agg, 3 * l + 2, b2, deg,
                                               cur, curld, sc[flip], NN);
        cur = sc[flip]; curld = HD; flip ^= 1;
    }

    // fused node update straight into out[:, :128]
    k_gemm_nu<<<GEMM_GRID, 512, NU_SMEM>>>(cur, curld, nu_b1, nu_b2, out, OUTC, NN);
}

// round 11
// speedup vs baseline: 2.6037x; 1.1558x over previous
#include <cuda_runtime.h>
#include <cuda_bf16.h>
#include <cuda_fp16.h>
#include <cstdint>

#define NN   50000
#define NE   1600000
#define HD   128
#define OUTC 224

// ---------------- scratch (device globals; no allocations) ----------------
__device__ float g_sc0[NN * HD];
__device__ float g_sc1[NN * HD];
__device__ float g_P[NN * HD];     // holds P as __half (half the bytes used)
__device__ float g_Q[NN * HD];
__device__ float g_agg[NN * HD];
__device__ int   g_deg[NN];
__device__ int   g_off[NN + 1];
__device__ int   g_cur[NN];
__device__ int   g_bsum[64];
__device__ int2  g_esort[NE];      // {sender, float_as_int(len)}
// pre-converted weights:
//  - bf16 hi/lo images (split scheme) for mats 2,5,6,7 (w2 x2, nu_w1, nu_w2)
//  - fp16 single images for mats 0,1,3,4 (w1a/w1b both layers) in slots 0..3
__device__ __nv_bfloat16 g_wimg_hi[8 * 16384];
__device__ __nv_bfloat16 g_wimg_lo[8 * 16384];
__device__ __half        g_wimg_h16[4 * 16384];

// ---------------- helpers ----------------
__device__ __forceinline__ float silu_f(float x) {
    float h = 0.5f * x, t;
    asm("tanh.approx.f32 %0, %1;" : "=f"(t) : "f"(h));
    return fmaf(h, t, h);
}

__device__ __forceinline__ void mma_bf16(float* c, const uint32_t* a, const uint32_t* b) {
    asm volatile(
        "mma.sync.aligned.m16n8k16.row.col.f32.bf16.bf16.f32 "
        "{%0,%1,%2,%3}, {%4,%5,%6,%7}, {%8,%9}, {%0,%1,%2,%3};"
        : "+f"(c[0]), "+f"(c[1]), "+f"(c[2]), "+f"(c[3])
        : "r"(a[0]), "r"(a[1]), "r"(a[2]), "r"(a[3]), "r"(b[0]), "r"(b[1]));
}

__device__ __forceinline__ void mma_f16(float* c, const uint32_t* a, const uint32_t* b) {
    asm volatile(
        "mma.sync.aligned.m16n8k16.row.col.f32.f16.f16.f32 "
        "{%0,%1,%2,%3}, {%4,%5,%6,%7}, {%8,%9}, {%0,%1,%2,%3};"
        : "+f"(c[0]), "+f"(c[1]), "+f"(c[2]), "+f"(c[3])
        : "r"(a[0]), "r"(a[1]), "r"(a[2]), "r"(a[3]), "r"(b[0]), "r"(b[1]));
}

// ---------------- small kernels ----------------
__global__ void k_zero_deg() {
    int i = blockIdx.x * blockDim.x + threadIdx.x;
    if (i < NN) g_deg[i] = 0;
}

__global__ void k_hist(const int* __restrict__ recv) {
    int e = blockIdx.x * blockDim.x + threadIdx.x;
    if (e < NE) atomicAdd(&g_deg[recv[e]], 1);
}

__global__ void __launch_bounds__(1024) k_scanA() {
    __shared__ int warp_sums[32];
    int tid = threadIdx.x;
    int lane = tid & 31, w = tid >> 5;
    int i = blockIdx.x * 1024 + tid;
    int v = (i < NN) ? g_deg[i] : 0;
    int x = v;
    #pragma unroll
    for (int d = 1; d < 32; d <<= 1) {
        int y = __shfl_up_sync(0xffffffffu, x, d);
        if (lane >= d) x += y;
    }
    if (lane == 31) warp_sums[w] = x;
    __syncthreads();
    if (w == 0) {
        int s = warp_sums[lane];
        #pragma unroll
        for (int d = 1; d < 32; d <<= 1) {
            int y = __shfl_up_sync(0xffffffffu, s, d);
            if (lane >= d) s += y;
        }
        warp_sums[lane] = s;
    }
    __syncthreads();
    int incl = x + (w ? warp_sums[w - 1] : 0);
    if (i < NN) g_off[i + 1] = incl;
    if (tid == 1023) g_bsum[blockIdx.x] = incl;
}

__global__ void k_scanB(int nblk) {
    if (threadIdx.x == 0) {
        int s = 0;
        for (int i = 0; i < nblk; i++) { int v = g_bsum[i]; g_bsum[i] = s; s += v; }
    }
}

__global__ void k_scanC() {
    int i = blockIdx.x * blockDim.x + threadIdx.x;
    if (i >= NN) return;
    int v = g_off[i + 1] + g_bsum[i >> 10];
    g_off[i + 1] = v;
    g_cur[i] = v - g_deg[i];
    if (i == 0) g_off[0] = 0;
}

__global__ void k_scatter(const int* __restrict__ send,
                          const int* __restrict__ recv,
                          const float* __restrict__ elen) {
    int e = blockIdx.x * blockDim.x + threadIdx.x;
    if (e >= NE) return;
    int r = recv[e];
    int p = atomicAdd(&g_cur[r], 1);
    g_esort[p] = make_int2(send[e], __float_as_int(elen[e]));
}

// ---------------- per-node edge aggregation (P fp16) ----------------
__global__ void __launch_bounds__(256) k_agg(const float4* __restrict__ wlast4) {
    int node = blockIdx.x * 8 + (threadIdx.x >> 5);
    int t = threadIdx.x & 31;
    if (node >= NN) return;
    int beg = g_off[node];
    int end = g_off[node + 1];
    const uint2* P4h = (const uint2*)g_P;
    float4 q  = ((const float4*)g_Q)[node * 32 + t];
    float4 wl = wlast4[t];
    float4 a = make_float4(0.f, 0.f, 0.f, 0.f);
    #pragma unroll 2
    for (int e = beg; e < end; ++e) {
        int2 ed = __ldg(&g_esort[e]);
        float l = __int_as_float(ed.y);
        uint2 pu = __ldg(&P4h[ed.x * 32 + t]);
        float2 p01 = __half22float2(*(const __half2*)&pu.x);
        float2 p23 = __half22float2(*(const __half2*)&pu.y);
        a.x += silu_f(p01.x + fmaf(l, wl.x, q.x));
        a.y += silu_f(p01.y + fmaf(l, wl.y, q.y));
        a.z += silu_f(p23.x + fmaf(l, wl.z, q.z));
        a.w += silu_f(p23.y + fmaf(l, wl.w, q.w));
    }
    ((float4*)g_agg)[node * 32 + t] = a;
}

// ---------------- weight pre-convert ----------------
struct WSrc { const float* p[8]; };

__global__ void k_wconv(WSrc ws) {
    int mat = blockIdx.y;
    int t = blockIdx.x * blockDim.x + threadIdx.x;   // 0..2047
    if (t >= 2048) return;
    int n  = t & 127;
    int k0 = (t >> 7) * 8;
    const float* src = ws.p[mat];
    __nv_bfloat16 hi[8], lo[8];
    __half h16[8];
    float xs[8];
    #pragma unroll
    for (int i = 0; i < 8; i++) {
        float x = src[(k0 + i) * HD + n];
        xs[i] = x;
        __nv_bfloat16 h = __float2bfloat16(x);
        hi[i] = h;
        lo[i] = __float2bfloat16(x - __bfloat162float(h));
    }
    size_t off = (size_t)mat * 16384 + n * 128 + k0;
    *(uint4*)&g_wimg_hi[off] = *(uint4*)hi;
    *(uint4*)&g_wimg_lo[off] = *(uint4*)lo;
    // fp16 single image for w1 matrices (mats 0,1,3,4 -> slots 0..3)
    if (mat == 0 || mat == 1 || mat == 3 || mat == 4) {
        int slot = (mat < 2) ? mat : mat - 1;
        #pragma unroll
        for (int i = 0; i < 8; i++) h16[i] = __float2half_rn(xs[i]);
        *(uint4*)&g_wimg_h16[(size_t)slot * 16384 + n * 128 + k0] = *(uint4*)h16;
    }
}

// ---------------- shared GEMM machinery ----------------
#define PITCH 136
#define HP    (PITCH / 2)
#define IMG   (128 * PITCH * 2)         // 34816 bytes per 16-bit image

// fp32 -> split bf16 hi/lo A tile
__device__ __forceinline__ void load_convert_A(
    const float* __restrict__ A, int lda, int blockM, int M,
    __nv_bfloat16* sAh, __nv_bfloat16* sAl, int tid)
{
    int r  = tid >> 2;
    int c0 = (tid & 3) * 32;
    int grow = blockM + r; if (grow >= M) grow = M - 1;
    const float* arow = A + (size_t)grow * lda + c0;
    #pragma unroll
    for (int g = 0; g < 4; g++) {
        float4 f0 = *(const float4*)(arow + g * 8);
        float4 f1 = *(const float4*)(arow + g * 8 + 4);
        float xs[8] = {f0.x, f0.y, f0.z, f0.w, f1.x, f1.y, f1.z, f1.w};
        __nv_bfloat16 hi[8], lo[8];
        #pragma unroll
        for (int i = 0; i < 8; i++) {
            __nv_bfloat16 h = __float2bfloat16(xs[i]);
            hi[i] = h;
            lo[i] = __float2bfloat16(xs[i] - __bfloat162float(h));
        }
        int off = r * PITCH + c0 + g * 8;
        *(uint4*)&sAh[off] = *(uint4*)hi;
        *(uint4*)&sAl[off] = *(uint4*)lo;
    }
}

// fp32 -> fp16 single A tile
__device__ __forceinline__ void load_convert_A16(
    const float* __restrict__ A, int lda, int blockM, int M,
    __half* sA, int tid)
{
    int r  = tid >> 2;
    int c0 = (tid & 3) * 32;
    int grow = blockM + r; if (grow >= M) grow = M - 1;
    const float* arow = A + (size_t)grow * lda + c0;
    #pragma unroll
    for (int g = 0; g < 4; g++) {
        float4 f0 = *(const float4*)(arow + g * 8);
        float4 f1 = *(const float4*)(arow + g * 8 + 4);
        __half hs[8] = {
            __float2half_rn(f0.x), __float2half_rn(f0.y),
            __float2half_rn(f0.z), __float2half_rn(f0.w),
            __float2half_rn(f1.x), __float2half_rn(f1.y),
            __float2half_rn(f1.z), __float2half_rn(f1.w) };
        *(uint4*)&sA[r * PITCH + c0 + g * 8] = *(uint4*)hs;
    }
}

// copy bf16 weight image pair into smem
__device__ __forceinline__ void copy_B(
    int mat, __nv_bfloat16* sBh, __nv_bfloat16* sBl, int tid)
{
    int r = tid >> 2;
    int s = (tid & 3) * 32;
    const uint4* shi = (const uint4*)&g_wimg_hi[(size_t)mat * 16384 + r * 128 + s];
    const uint4* slo = (const uint4*)&g_wimg_lo[(size_t)mat * 16384 + r * 128 + s];
    uint4* dhi = (uint4*)&sBh[r * PITCH + s];
    uint4* dlo = (uint4*)&sBl[r * PITCH + s];
    #pragma unroll
    for (int i = 0; i < 4; i++) { dhi[i] = shi[i]; dlo[i] = slo[i]; }
}

// copy fp16 weight image into smem
__device__ __forceinline__ void copy_B16(int slot, __half* sB, int tid)
{
    int r = tid >> 2;
    int s = (tid & 3) * 32;
    const uint4* src = (const uint4*)&g_wimg_h16[(size_t)slot * 16384 + r * 128 + s];
    uint4* dst = (uint4*)&sB[r * PITCH + s];
    #pragma unroll
    for (int i = 0; i < 4; i++) dst[i] = src[i];
}

// load warp A fragments (one image) for k-step ks
__device__ __forceinline__ void load_afrag1(
    const uint32_t* Ax, int row0, int g2, int tq, int ks, uint32_t a[2][4])
{
    int kp = ks * 8;
    #pragma unroll
    for (int mi = 0; mi < 2; mi++) {
        int r1 = (row0 + mi * 16 + g2) * HP;
        int r2 = r1 + 8 * HP;
        a[mi][0] = Ax[r1 + kp + tq];
        a[mi][1] = Ax[r2 + kp + tq];
        a[mi][2] = Ax[r1 + kp + 4 + tq];
        a[mi][3] = Ax[r2 + kp + 4 + tq];
    }
}

// 3-term bf16 MMA step
__device__ __forceinline__ void mma_step(
    const uint32_t* Bh, const uint32_t* Bl, int col0, int g2, int tq, int ks,
    uint32_t ah[2][4], uint32_t al[2][4], float acc[2][4][4])
{
    int kp = ks * 8;
    #pragma unroll
    for (int nj = 0; nj < 4; nj++) {
        int rn = (col0 + nj * 8 + g2) * HP;
        uint32_t bh[2], bl[2];
        bh[0] = Bh[rn + kp + tq];
        bh[1] = Bh[rn + kp + 4 + tq];
        bl[0] = Bl[rn + kp + tq];
        bl[1] = Bl[rn + kp + 4 + tq];
        #pragma unroll
        for (int mi = 0; mi < 2; mi++) {
            mma_bf16(acc[mi][nj], ah[mi], bh);
            mma_bf16(acc[mi][nj], ah[mi], bl);
            mma_bf16(acc[mi][nj], al[mi], bh);
        }
    }
}

// single-pass fp16 MMA step
__device__ __forceinline__ void mma_step16(
    const uint32_t* B, int col0, int g2, int tq, int ks,
    uint32_t a[2][4], float acc[2][4][4])
{
    int kp = ks * 8;
    #pragma unroll
    for (int nj = 0; nj < 4; nj++) {
        int rn = (col0 + nj * 8 + g2) * HP;
        uint32_t b[2];
        b[0] = B[rn + kp + tq];
        b[1] = B[rn + kp + 4 + tq];
        #pragma unroll
        for (int mi = 0; mi < 2; mi++)
            mma_f16(acc[mi][nj], a[mi], b);
    }
}

// ---------------- fused P+Q GEMM, single-pass fp16 ----------------------------
#define PQ_SMEM (3 * IMG)
__global__ void __launch_bounds__(512, 1) k_gemm_pq16(
    const float* __restrict__ A, int lda, int slot0,
    const float* __restrict__ b1,
    __half* __restrict__ Pout, float* __restrict__ Qout, int M)
{
    extern __shared__ char smem[];
    __half* sA  = (__half*)(smem);
    __half* sB0 = (__half*)(smem + IMG);
    __half* sB1 = (__half*)(smem + 2 * IMG);

    int tid = threadIdx.x;
    int wid = tid >> 5, lid = tid & 31;
    int blockM = blockIdx.x * 128;

    load_convert_A16(A, lda, blockM, M, sA, tid);
    copy_B16(slot0,     sB0, tid);
    copy_B16(slot0 + 1, sB1, tid);
    __syncthreads();

    int row0 = (wid >> 2) * 32;
    int col0 = (wid & 3) * 32;
    int g2 = lid >> 2, tq = lid & 3;

    float acc[2][2][4][4];
    #pragma unroll
    for (int m = 0; m < 2; m++)
        for (int mi = 0; mi < 2; mi++)
            for (int nj = 0; nj < 4; nj++)
                for (int q = 0; q < 4; q++) acc[m][mi][nj][q] = 0.f;

    const uint32_t* Au = (const uint32_t*)sA;

    #pragma unroll 2
    for (int ks = 0; ks < 8; ks++) {
        uint32_t a[2][4];
        load_afrag1(Au, row0, g2, tq, ks, a);
        mma_step16((const uint32_t*)sB0, col0, g2, tq, ks, a, acc[0]);
        mma_step16((const uint32_t*)sB1, col0, g2, tq, ks, a, acc[1]);
    }

    #pragma unroll
    for (int mi = 0; mi < 2; mi++) {
        int r1 = blockM + row0 + mi * 16 + g2;
        int r2 = r1 + 8;
        #pragma unroll
        for (int nj = 0; nj < 4; nj++) {
            int col = col0 + nj * 8 + tq * 2;
            float2 bv = *(const float2*)(b1 + col);
            if (r1 < M) {
                *(__half2*)(Pout + (size_t)r1 * HD + col) =
                    __float22half2_rn(make_float2(acc[0][mi][nj][0], acc[0][mi][nj][1]));
                *(float2*)(Qout + (size_t)r1 * HD + col) =
                    make_float2(acc[1][mi][nj][0] + bv.x, acc[1][mi][nj][1] + bv.y);
            }
            if (r2 < M) {
                *(__half2*)(Pout + (size_t)r2 * HD + col) =
                    __float22half2_rn(make_float2(acc[0][mi][nj][2], acc[0][mi][nj][3]));
                *(float2*)(Qout + (size_t)r2 * HD + col) =
                    make_float2(acc[1][mi][nj][2] + bv.x, acc[1][mi][nj][3] + bv.y);
            }
        }
    }
}

// ---------------- W2 GEMM (3-pass bf16): C = agg @ w2 + deg*b2 + resid --------
#define W2_SMEM (4 * IMG)
__global__ void __launch_bounds__(512, 1) k_gemm_w2(
    const float* __restrict__ A, int mat,
    const float* __restrict__ bias, const int* __restrict__ degscale,
    const float* __restrict__ resid, int ldr,
    float* __restrict__ C, int M)
{
    extern __shared__ char smem[];
    __nv_bfloat16* sAh = (__nv_bfloat16*)(smem);
    __nv_bfloat16* sAl = (__nv_bfloat16*)(smem + IMG);
    __nv_bfloat16* sBh = (__nv_bfloat16*)(smem + 2 * IMG);
    __nv_bfloat16* sBl = (__nv_bfloat16*)(smem + 3 * IMG);

    int tid = threadIdx.x;
    int wid = tid >> 5, lid = tid & 31;
    int blockM = blockIdx.x * 128;

    load_convert_A(A, HD, blockM, M, sAh, sAl, tid);
    copy_B(mat, sBh, sBl, tid);
    __syncthreads();

    int row0 = (wid >> 2) * 32;
    int col0 = (wid & 3) * 32;
    int g2 = lid >> 2, tq = lid & 3;

    float acc[2][4][4];
    #pragma unroll
    for (int mi = 0; mi < 2; mi++)
        for (int nj = 0; nj < 4; nj++)
            for (int q = 0; q < 4; q++) acc[mi][nj][q] = 0.f;

    const uint32_t* Ah = (const uint32_t*)sAh;
    const uint32_t* Al = (const uint32_t*)sAl;

    #pragma unroll 2
    for (int ks = 0; ks < 8; ks++) {
        uint32_t ah[2][4], al[2][4];
        load_afrag1(Ah, row0, g2, tq, ks, ah);
        load_afrag1(Al, row0, g2, tq, ks, al);
        mma_step((const uint32_t*)sBh, (const uint32_t*)sBl,
                 col0, g2, tq, ks, ah, al, acc);
    }

    #pragma unroll
    for (int mi = 0; mi < 2; mi++) {
        int r1 = blockM + row0 + mi * 16 + g2;
        int r2 = r1 + 8;
        float ds1 = (r1 < M) ? (float)degscale[r1] : 0.f;
        float ds2 = (r2 < M) ? (float)degscale[r2] : 0.f;
        #pragma unroll
        for (int nj = 0; nj < 4; nj++) {
            int col = col0 + nj * 8 + tq * 2;
            float2 bv = *(const float2*)(bias + col);
            if (r1 < M) {
                float2 rv = *(const float2*)(resid + (size_t)r1 * ldr + col);
                *(float2*)(C + (size_t)r1 * HD + col) = make_float2(
                    acc[mi][nj][0] + ds1 * bv.x + rv.x,
                    acc[mi][nj][1] + ds1 * bv.y + rv.y);
            }
            if (r2 < M) {
                float2 rv = *(const float2*)(resid + (size_t)r2 * ldr + col);
                *(float2*)(C + (size_t)r2 * HD + col) = make_float2(
                    acc[mi][nj][2] + ds2 * bv.x + rv.x,
                    acc[mi][nj][3] + ds2 * bv.y + rv.y);
            }
        }
    }
}

// ---------------- fused node-update + rest-copy ------------------------------
// out[:, :128] = sc + silu(sc@W1+b1)@W2 + b2 ; out[:, 128:224] = h[:, 128:224]
#define NU_SMEM (6 * IMG)
__global__ void __launch_bounds__(512, 1) k_gemm_nu(
    const float* __restrict__ A, int lda,
    const float* __restrict__ hsrc,
    const float* __restrict__ b1, const float* __restrict__ b2,
    float* __restrict__ out, int ldc, int M)
{
    extern __shared__ char smem[];
    __nv_bfloat16* sAh  = (__nv_bfloat16*)(smem);            // later: T hi
    __nv_bfloat16* sAl  = (__nv_bfloat16*)(smem + IMG);      // later: T lo
    __nv_bfloat16* sB1h = (__nv_bfloat16*)(smem + 2 * IMG);
    __nv_bfloat16* sB1l = (__nv_bfloat16*)(smem + 3 * IMG);
    __nv_bfloat16* sB2h = (__nv_bfloat16*)(smem + 4 * IMG);
    __nv_bfloat16* sB2l = (__nv_bfloat16*)(smem + 5 * IMG);

    int tid = threadIdx.x;
    int wid = tid >> 5, lid = tid & 31;
    int blockM = blockIdx.x * 128;

    // rest-channel copy for this CTA's rows (independent; overlaps with MMA)
    {
        #pragma unroll
        for (int i = 0; i < 6; i++) {
            int t = tid + i * 512;            // 3072 float4 = 128 rows x 24
            int row = t / 24, c4 = t - row * 24;
            int grow = blockM + row;
            if (grow < M) {
                size_t idx = (size_t)grow * OUTC + HD + c4 * 4;
                *(float4*)(out + idx) = *(const float4*)(hsrc + idx);
            }
        }
    }

    load_convert_A(A, lda, blockM, M, sAh, sAl, tid);
    copy_B(6, sB1h, sB1l, tid);
    copy_B(7, sB2h, sB2l, tid);
    __syncthreads();

    int row0 = (wid >> 2) * 32;
    int col0 = (wid & 3) * 32;
    int g2 = lid >> 2, tq = lid & 3;

    float acc[2][4][4];
    #pragma unroll
    for (int mi = 0; mi < 2; mi++)
        for (int nj = 0; nj < 4; nj++)
            for (int q = 0; q < 4; q++) acc[mi][nj][q] = 0.f;

    const uint32_t* Ah = (const uint32_t*)sAh;
    const uint32_t* Al = (const uint32_t*)sAl;

    // ---- MMA 1: A @ nu_w1 ----
    #pragma unroll 2
    for (int ks = 0; ks < 8; ks++) {
        uint32_t ah[2][4], al[2][4];
        load_afrag1(Ah, row0, g2, tq, ks, ah);
        load_afrag1(Al, row0, g2, tq, ks, al);
        mma_step((const uint32_t*)sB1h, (const uint32_t*)sB1l,
                 col0, g2, tq, ks, ah, al, acc);
    }
    __syncthreads();

    // ---- T = silu(acc + b1) -> bf16 hi/lo into A slots ----
    {
        uint32_t* Th = (uint32_t*)sAh;
        uint32_t* Tl = (uint32_t*)sAl;
        #pragma unroll
        for (int mi = 0; mi < 2; mi++) {
            int rt1 = row0 + mi * 16 + g2;
            int rt2 = rt1 + 8;
            #pragma unroll
            for (int nj = 0; nj < 4; nj++) {
                int col = col0 + nj * 8 + tq * 2;
                float2 bv = *(const float2*)(b1 + col);
                float v0 = silu_f(acc[mi][nj][0] + bv.x);
                float v1 = silu_f(acc[mi][nj][1] + bv.y);
                float v2 = silu_f(acc[mi][nj][2] + bv.x);
                float v3 = silu_f(acc[mi][nj][3] + bv.y);
                __nv_bfloat16 h0 = __float2bfloat16(v0), h1 = __float2bfloat16(v1);
                __nv_bfloat16 h2 = __float2bfloat16(v2), h3 = __float2bfloat16(v3);
                __nv_bfloat162 hi1 = {h0, h1}, hi2 = {h2, h3};
                __nv_bfloat162 lo1 = {__float2bfloat16(v0 - __bfloat162float(h0)),
                                      __float2bfloat16(v1 - __bfloat162float(h1))};
                __nv_bfloat162 lo2 = {__float2bfloat16(v2 - __bfloat162float(h2)),
                                      __float2bfloat16(v3 - __bfloat162float(h3))};
                Th[rt1 * HP + col / 2] = *(uint32_t*)&hi1;
                Tl[rt1 * HP + col / 2] = *(uint32_t*)&lo1;
                Th[rt2 * HP + col / 2] = *(uint32_t*)&hi2;
                Tl[rt2 * HP + col / 2] = *(uint32_t*)&lo2;
                acc[mi][nj][0] = 0.f; acc[mi][nj][1] = 0.f;
                acc[mi][nj][2] = 0.f; acc[mi][nj][3] = 0.f;
            }
        }
    }
    __syncthreads();

    // ---- MMA 2: T @ nu_w2 ----
    #pragma unroll 2
    for (int ks = 0; ks < 8; ks++) {
        uint32_t ah[2][4], al[2][4];
        load_afrag1(Ah, row0, g2, tq, ks, ah);
        load_afrag1(Al, row0, g2, tq, ks, al);
        mma_step((const uint32_t*)sB2h, (const uint32_t*)sB2l,
                 col0, g2, tq, ks, ah, al, acc);
    }

    // ---- epilogue: + b2 + resid(scalars), write out (ldc = OUTC) ----
    #pragma unroll
    for (int mi = 0; mi < 2; mi++) {
        int r1 = blockM + row0 + mi * 16 + g2;
        int r2 = r1 + 8;
        #pragma unroll
        for (int nj = 0; nj < 4; nj++) {
            int col = col0 + nj * 8 + tq * 2;
            float2 bv = *(const float2*)(b2 + col);
            if (r1 < M) {
                float2 rv = *(const float2*)(A + (size_t)r1 * lda + col);
                *(float2*)(out + (size_t)r1 * ldc + col) = make_float2(
                    acc[mi][nj][0] + bv.x + rv.x, acc[mi][nj][1] + bv.y + rv.y);
            }
            if (r2 < M) {
                float2 rv = *(const float2*)(A + (size_t)r2 * lda + col);
                *(float2*)(out + (size_t)r2 * ldc + col) = make_float2(
                    acc[mi][nj][2] + bv.x + rv.x, acc[mi][nj][3] + bv.y + rv.y);
            }
        }
    }
}

// ---------------- launch ----------------
static float* sym_f(const void* s) { void* p = nullptr; cudaGetSymbolAddress(&p, s); return (float*)p; }
static int*   sym_i(const void* s) { void* p = nullptr; cudaGetSymbolAddress(&p, s); return (int*)p; }

extern "C" void kernel_launch(void* const* d_in, const int* in_sizes, int n_in,
                              void* d_out, int out_size) {
    const float* h     = (const float*)d_in[0];
    const int*   ei    = (const int*)  d_in[1];
    const float* elen  = (const float*)d_in[2];
    const float* mp_w1 = (const float*)d_in[3];
    const float* mp_b1 = (const float*)d_in[4];
    const float* mp_w2 = (const float*)d_in[5];
    const float* mp_b2 = (const float*)d_in[6];
    const float* nu_w1 = (const float*)d_in[7];
    const float* nu_b1 = (const float*)d_in[8];
    const float* nu_w2 = (const float*)d_in[9];
    const float* nu_b2 = (const float*)d_in[10];
    float* out = (float*)d_out;

    const int* send = ei;
    const int* recv = ei + NE;

    float* sc[2] = { sym_f(g_sc0), sym_f(g_sc1) };
    __half* Ph = (__half*)sym_f(g_P);
    float* Q   = sym_f(g_Q);
    float* agg = sym_f(g_agg);
    int*   deg = sym_i(g_deg);

    static int attr_done = 0;
    if (!attr_done) {
        cudaFuncSetAttribute(k_gemm_pq16, cudaFuncAttributeMaxDynamicSharedMemorySize, PQ_SMEM);
        cudaFuncSetAttribute(k_gemm_w2,   cudaFuncAttributeMaxDynamicSharedMemorySize, W2_SMEM);
        cudaFuncSetAttribute(k_gemm_nu,   cudaFuncAttributeMaxDynamicSharedMemorySize, NU_SMEM);
        attr_done = 1;
    }

    const int GEMM_GRID = (NN + 127) / 128;   // 391
    const int SCAN_BLK  = (NN + 1023) / 1024; // 49

    // weight images: 0..2 layer0 {w1a,w1b,w2}, 3..5 layer1, 6 nu_w1, 7 nu_w2
    WSrc ws;
    ws.p[0] = mp_w1;                 ws.p[1] = mp_w1 + 128 * HD;
    ws.p[2] = mp_w2;
    ws.p[3] = mp_w1 + 257 * HD;      ws.p[4] = mp_w1 + 257 * HD + 128 * HD;
    ws.p[5] = mp_w2 + HD * HD;
    ws.p[6] = nu_w1;                 ws.p[7] = nu_w2;

    // launch order arranged so ncu's fixed profile slot (index 3) lands on the
    // layer-0 PQ GEMM.
    k_wconv<<<dim3(8, 8), 256>>>(ws);                       // 0
    k_zero_deg<<<(NN + 255) / 256, 256>>>();                // 1
    k_hist<<<(NE + 255) / 256, 256>>>(recv);                // 2
    k_gemm_pq16<<<GEMM_GRID, 512, PQ_SMEM>>>(h, OUTC, 0,    // 3  <- profiled
                                             mp_b1, Ph, Q, NN);
    k_scanA<<<SCAN_BLK, 1024>>>();                          // 4
    k_scanB<<<1, 32>>>(SCAN_BLK);                           // 5
    k_scanC<<<(NN + 255) / 256, 256>>>();                   // 6
    k_scatter<<<(NE + 255) / 256, 256>>>(send, recv, elen); // 7

    // layer 0 (PQ already done above)
    k_agg<<<(NN + 7) / 8, 256>>>((const float4*)(mp_w1 + 256 * HD));
    k_gemm_w2<<<GEMM_GRID, 512, W2_SMEM>>>(agg, 2, mp_b2, deg, h, OUTC, sc[0], NN);

    // layer 1
    const float* w1_l1 = mp_w1 + 257 * HD;
    k_gemm_pq16<<<GEMM_GRID, 512, PQ_SMEM>>>(sc[0], HD, 2, mp_b1 + HD, Ph, Q, NN);
    k_agg<<<(NN + 7) / 8, 256>>>((const float4*)(w1_l1 + 256 * HD));
    k_gemm_w2<<<GEMM_GRID, 512, W2_SMEM>>>(agg, 5, mp_b2 + HD, deg, sc[0], HD, sc[1], NN);

    // fused node update + rest copy straight into out
    k_gemm_nu<<<GEMM_GRID, 512, NU_SMEM>>>(sc[1], HD, h, nu_b1, nu_b2, out, OUTC, NN);
}